// round 6
// baseline (speedup 1.0000x reference)
#include <cuda_runtime.h>
#include <cuda_bf16.h>

// Problem constants
#define T_  1024
#define H_  2048
#define I_  768
#define E_  32
#define K_  4
#define NA  (T_*K_)   // 4096 assignment rows

#define KC  32
#define RS  80        // SMEM row stride bytes (32 bf16 + 16B pad) — conflict-free ldmatrix

// ---------------- portable PTX helpers ----------------
__device__ __forceinline__ unsigned smem_u32(const void* p) {
    unsigned a;
    asm("{ .reg .u64 t; cvta.to.shared.u64 t, %1; cvt.u32.u64 %0, t; }" : "=r"(a) : "l"(p));
    return a;
}

__device__ __forceinline__ void ldm4(unsigned* d, unsigned a) {
    asm volatile("ldmatrix.sync.aligned.m8n8.x4.shared.b16 {%0,%1,%2,%3}, [%4];"
        : "=r"(d[0]), "=r"(d[1]), "=r"(d[2]), "=r"(d[3]) : "r"(a));
}

__device__ __forceinline__ void mma4(float* c, const unsigned* a, const unsigned* b) {
    asm volatile("mma.sync.aligned.m16n8k16.row.col.f32.bf16.bf16.f32 "
        "{%0,%1,%2,%3},{%4,%5,%6,%7},{%8,%9},{%0,%1,%2,%3};"
        : "+f"(c[0]), "+f"(c[1]), "+f"(c[2]), "+f"(c[3])
        : "r"(a[0]), "r"(a[1]), "r"(a[2]), "r"(a[3]), "r"(b[0]), "r"(b[1]));
}

__device__ __forceinline__ void cpasync16(unsigned saddr, const void* g) {
    asm volatile("cp.async.ca.shared.global [%0], [%1], 16;" :: "r"(saddr), "l"(g));
}
#define CP_COMMIT() asm volatile("cp.async.commit_group;")
#define CP_WAIT0()  asm volatile("cp.async.wait_group 0;")

// split 8 fp32 -> 8 bf16 hi + 8 bf16 lo
__device__ __forceinline__ void cvt8(float4 a, float4 b, uint4& hi, uint4& lo) {
    float va[8] = {a.x, a.y, a.z, a.w, b.x, b.y, b.z, b.w};
    unsigned hw[4], lw[4];
#pragma unroll
    for (int j = 0; j < 4; j++) {
        float2 f = make_float2(va[2*j], va[2*j+1]);
        __nv_bfloat162 h = __float22bfloat162_rn(f);
        float2 hf = __bfloat1622float2(h);
        __nv_bfloat162 l = __float22bfloat162_rn(make_float2(f.x - hf.x, f.y - hf.y));
        hw[j] = *reinterpret_cast<unsigned*>(&h);
        lw[j] = *reinterpret_cast<unsigned*>(&l);
    }
    hi = make_uint4(hw[0], hw[1], hw[2], hw[3]);
    lo = make_uint4(lw[0], lw[1], lw[2], lw[3]);
}

// ---- device scratch ----
__device__ int   g_counts[E_];
__device__ int   g_offsets[E_];
__device__ int   g_perm[NA];
__device__ __align__(16) __nv_bfloat16 g_h_hi[(size_t)NA * I_];
__device__ __align__(16) __nv_bfloat16 g_h_lo[(size_t)NA * I_];
__device__ __align__(16) float g_yp[(size_t)NA * H_];

// ---------------- routing ----------------
__global__ void k_route(const int* __restrict__ ids) {
    __shared__ int cnt[E_], offs[E_], cur[E_];
    int tid = threadIdx.x;   // 1024
    if (tid < E_) { cnt[tid] = 0; cur[tid] = 0; }
    __syncthreads();
    for (int i = tid; i < NA; i += 1024) atomicAdd(&cnt[ids[i]], 1);
    __syncthreads();
    if (tid == 0) {
        int acc = 0;
        for (int e = 0; e < E_; e++) {
            offs[e] = acc; g_offsets[e] = acc; g_counts[e] = cnt[e]; acc += cnt[e];
        }
    }
    __syncthreads();
    for (int i = tid; i < NA; i += 1024) {
        int e = ids[i];
        int p = atomicAdd(&cur[e], 1);
        g_perm[offs[e] + p] = i;
    }
}

// ---------------- gate+up mma GEMM: 128 x 64 tile ----------------
// Stage (40960 B): A_hi 0 (10240), A_lo 10240, Bg_hi 20480 (5120),
// Bg_lo 25600, Bu_hi 30720, Bu_lo 35840. Double buffered.
#define GU_STAGE 40960
#define GU_SMEM  (2*GU_STAGE + 1024)
#define HST      144           // h-stage row stride: 64 bf16 (128 B) + 16 B pad, 16-aligned

__global__ void __launch_bounds__(256, 2) k_gateup_mma(
    const float* __restrict__ x,
    const float* __restrict__ Wg,
    const float* __restrict__ Wu)
{
    int e    = blockIdx.z;
    int cnt  = g_counts[e];
    int row0 = blockIdx.y * 128;
    if (row0 >= cnt) return;
    int off  = g_offsets[e];
    int col0 = blockIdx.x * 64;

    extern __shared__ char smem[];
    unsigned sb = smem_u32(smem);
    int tid = threadIdx.x;
    int wid = tid >> 5, l = tid & 31;
    int wm = wid & 3, wn = wid >> 2;   // 4 x 2 warp grid, warp tile 32x32

    int* toks = (int*)(smem + 2*GU_STAGE);
    if (tid < 128) {
        int r = row0 + tid;
        toks[tid] = g_perm[off + ((r < cnt) ? r : (cnt - 1))] >> 2;
    }
    __syncthreads();

    const float* wg = Wg + (size_t)e * I_ * H_ + (size_t)col0 * H_;
    const float* wu = Wu + (size_t)e * I_ * H_ + (size_t)col0 * H_;

    float cg[2][4][4], cu[2][4][4];
#pragma unroll
    for (int mt = 0; mt < 2; mt++)
#pragma unroll
        for (int nt = 0; nt < 4; nt++)
#pragma unroll
            for (int j = 0; j < 4; j++) { cg[mt][nt][j] = 0.f; cu[mt][nt][j] = 0.f; }

    // A fill: 128 rows x 32 cols fp32, 2 slots/thread (8 floats each)
    int ar0 = tid >> 2,          ac0 = (tid & 3) * 8;
    int ar1 = (tid + 256) >> 2,  ac1 = (tid & 3) * 8;
    // B fill: 64 rows x 32 cols, 1 slot/thread
    int br = tid >> 2, bc = (tid & 3) * 8;

    // ---- prologue: chunk 0 -> stage 0 ----
    {
        char* st = smem;
        uint4 hv, lv;
        const float* p;
        p = x + (size_t)toks[ar0] * H_ + ac0;
        cvt8(*(const float4*)p, *(const float4*)(p + 4), hv, lv);
        *(uint4*)(st + 0     + ar0*RS + ac0*2) = hv;
        *(uint4*)(st + 10240 + ar0*RS + ac0*2) = lv;
        p = x + (size_t)toks[ar1] * H_ + ac1;
        cvt8(*(const float4*)p, *(const float4*)(p + 4), hv, lv);
        *(uint4*)(st + 0     + ar1*RS + ac1*2) = hv;
        *(uint4*)(st + 10240 + ar1*RS + ac1*2) = lv;
        p = wg + (size_t)br * H_ + bc;
        cvt8(*(const float4*)p, *(const float4*)(p + 4), hv, lv);
        *(uint4*)(st + 20480 + br*RS + bc*2) = hv;
        *(uint4*)(st + 25600 + br*RS + bc*2) = lv;
        p = wu + (size_t)br * H_ + bc;
        cvt8(*(const float4*)p, *(const float4*)(p + 4), hv, lv);
        *(uint4*)(st + 30720 + br*RS + bc*2) = hv;
        *(uint4*)(st + 35840 + br*RS + bc*2) = lv;
    }
    __syncthreads();

    const int NK = H_ / KC;   // 64
    for (int k = 0; k < NK; k++) {
        int s = k & 1;
        bool pf = (k + 1 < NK);
        float4 pa0, pa1, pa2, pa3, pg0, pg1, pu0, pu1;
        if (pf) {
            int k0 = (k + 1) * KC;
            const float* p;
            p = x + (size_t)toks[ar0] * H_ + k0 + ac0; pa0 = *(const float4*)p; pa1 = *(const float4*)(p + 4);
            p = x + (size_t)toks[ar1] * H_ + k0 + ac1; pa2 = *(const float4*)p; pa3 = *(const float4*)(p + 4);
            p = wg + (size_t)br * H_ + k0 + bc; pg0 = *(const float4*)p; pg1 = *(const float4*)(p + 4);
            p = wu + (size_t)br * H_ + k0 + bc; pu0 = *(const float4*)p; pu1 = *(const float4*)(p + 4);
        }

        // ---- compute on stage s ----
        unsigned stb = sb + s * GU_STAGE;
#pragma unroll
        for (int kk = 0; kk < 2; kk++) {
            unsigned ah[2][4], al[2][4];
#pragma unroll
            for (int mt = 0; mt < 2; mt++) {
                unsigned arow = (unsigned)(wm*32 + mt*16 + (l & 15)) * RS;
                unsigned ak   = (unsigned)(kk*16 + ((l >> 4) << 3)) * 2;
                ldm4(ah[mt], stb + 0     + arow + ak);
                ldm4(al[mt], stb + 10240 + arow + ak);
            }
#pragma unroll
            for (int nt16 = 0; nt16 < 2; nt16++) {
                unsigned bro = (unsigned)(wn*32 + nt16*16 + ((l >> 4) & 1)*8 + (l & 7)) * RS
                             + (unsigned)(kk*16 + ((l >> 3) & 1)*8) * 2;
                unsigned bh[4], bl[4];
                ldm4(bh, stb + 20480 + bro);
                ldm4(bl, stb + 25600 + bro);
#pragma unroll
                for (int mt = 0; mt < 2; mt++) {
                    mma4(cg[mt][2*nt16],   ah[mt], bh);   mma4(cg[mt][2*nt16+1], ah[mt], bh+2);
                    mma4(cg[mt][2*nt16],   al[mt], bh);   mma4(cg[mt][2*nt16+1], al[mt], bh+2);
                    mma4(cg[mt][2*nt16],   ah[mt], bl);   mma4(cg[mt][2*nt16+1], ah[mt], bl+2);
                }
                ldm4(bh, stb + 30720 + bro);
                ldm4(bl, stb + 35840 + bro);
#pragma unroll
                for (int mt = 0; mt < 2; mt++) {
                    mma4(cu[mt][2*nt16],   ah[mt], bh);   mma4(cu[mt][2*nt16+1], ah[mt], bh+2);
                    mma4(cu[mt][2*nt16],   al[mt], bh);   mma4(cu[mt][2*nt16+1], al[mt], bh+2);
                    mma4(cu[mt][2*nt16],   ah[mt], bl);   mma4(cu[mt][2*nt16+1], ah[mt], bl+2);
                }
            }
        }

        if (pf) {
            char* st = smem + (s ^ 1) * GU_STAGE;
            uint4 hv, lv;
            cvt8(pa0, pa1, hv, lv);
            *(uint4*)(st + 0     + ar0*RS + ac0*2) = hv;
            *(uint4*)(st + 10240 + ar0*RS + ac0*2) = lv;
            cvt8(pa2, pa3, hv, lv);
            *(uint4*)(st + 0     + ar1*RS + ac1*2) = hv;
            *(uint4*)(st + 10240 + ar1*RS + ac1*2) = lv;
            cvt8(pg0, pg1, hv, lv);
            *(uint4*)(st + 20480 + br*RS + bc*2) = hv;
            *(uint4*)(st + 25600 + br*RS + bc*2) = lv;
            cvt8(pu0, pu1, hv, lv);
            *(uint4*)(st + 30720 + br*RS + bc*2) = hv;
            *(uint4*)(st + 35840 + br*RS + bc*2) = lv;
        }
        __syncthreads();
    }

    // ---- epilogue: h = silu(g)*u -> SMEM stage -> coalesced global ----
    char* sh_hi = smem;                 // 128 x HST = 18432
    char* sh_lo = smem + 128*HST;       // 18432 (total 36864 < 2*GU_STAGE)
#pragma unroll
    for (int mt = 0; mt < 2; mt++)
#pragma unroll
        for (int nt = 0; nt < 4; nt++)
#pragma unroll
            for (int half = 0; half < 2; half++) {
                int rr = wm*32 + mt*16 + (l >> 2) + half*8;
                int cc = wn*32 + nt*8 + (l & 3)*2;
                float g0 = cg[mt][nt][2*half],   g1 = cg[mt][nt][2*half+1];
                float u0 = cu[mt][nt][2*half],   u1 = cu[mt][nt][2*half+1];
                float h0 = (g0 / (1.f + __expf(-g0))) * u0;
                float h1 = (g1 / (1.f + __expf(-g1))) * u1;
                __nv_bfloat162 hb = __float22bfloat162_rn(make_float2(h0, h1));
                float2 hf = __bfloat1622float2(hb);
                __nv_bfloat162 lb = __float22bfloat162_rn(make_float2(h0 - hf.x, h1 - hf.y));
                *(unsigned*)(sh_hi + rr*HST + cc*2) = *reinterpret_cast<unsigned*>(&hb);
                *(unsigned*)(sh_lo + rr*HST + cc*2) = *reinterpret_cast<unsigned*>(&lb);
            }
    __syncthreads();
#pragma unroll
    for (int j = 0; j < 4; j++) {
        int u = tid + 256*j;            // 1024 slots: 128 rows x 8 uint4
        int r = u >> 3, c8 = u & 7;
        if (row0 + r < cnt) {
            size_t gidx = (size_t)(off + row0 + r) * I_ + col0 + c8*8;
            *(uint4*)&g_h_hi[gidx] = *(uint4*)(sh_hi + r*HST + c8*16);
            *(uint4*)&g_h_lo[gidx] = *(uint4*)(sh_lo + r*HST + c8*16);
        }
    }
}

// ---------------- down mma GEMM: 128 x 128 tile ----------------
// Stage (40960): A_hi 0 (10240), A_lo 10240, B_hi 20480 (10240), B_lo 30720.
#define DN_STAGE 40960
#define DN_SMEM  (2*DN_STAGE + 1024)

__global__ void __launch_bounds__(256, 2) k_down_mma(
    const float* __restrict__ Wd,
    const float* __restrict__ ew)
{
    int e    = blockIdx.z;
    int cnt  = g_counts[e];
    int row0 = blockIdx.y * 128;
    if (row0 >= cnt) return;
    int off  = g_offsets[e];
    int col0 = blockIdx.x * 128;

    extern __shared__ char smem[];
    unsigned sb = smem_u32(smem);
    int tid = threadIdx.x;
    int wid = tid >> 5, l = tid & 31;
    int wm = wid & 3, wn = wid >> 2;   // 4 x 2, warp tile 32 x 64

    int* pvS = (int*)(smem + 2*DN_STAGE);
    if (tid < 128) {
        int r = row0 + tid;
        pvS[tid] = (r < cnt) ? g_perm[off + r] : -1;
    }
    __syncthreads();

    const float* wd = Wd + (size_t)e * H_ * I_ + (size_t)col0 * I_;

    float cd[2][8][4];
#pragma unroll
    for (int mt = 0; mt < 2; mt++)
#pragma unroll
        for (int nt = 0; nt < 8; nt++)
#pragma unroll
            for (int j = 0; j < 4; j++) cd[mt][nt][j] = 0.f;

    // A fill via cp.async: 2 slots/thread of hi + 2 of lo (128 rows x 4 uint4)
    int as0 = tid, as1 = tid + 256;
    int aR0 = as0 >> 2, aC0 = (as0 & 3) * 8;
    int aR1 = as1 >> 2, aC1 = (as1 & 3) * 8;
    size_t gA0 = (size_t)(off + (((row0 + aR0) < cnt) ? (row0 + aR0) : (cnt - 1))) * I_;
    size_t gA1 = (size_t)(off + (((row0 + aR1) < cnt) ? (row0 + aR1) : (cnt - 1))) * I_;
    // B fill: 128 rows x 32 fp32, 2 slots/thread
    int bR0 = tid >> 2,        bC0 = (tid & 3) * 8;
    int bR1 = (tid + 256) >> 2, bC1 = (tid & 3) * 8;

    // prologue: chunk 0 -> stage 0
    {
        char* st = smem;
        unsigned stu = sb;
        cpasync16(stu + 0     + aR0*RS + aC0*2, &g_h_hi[gA0 + aC0]);
        cpasync16(stu + 0     + aR1*RS + aC1*2, &g_h_hi[gA1 + aC1]);
        cpasync16(stu + 10240 + aR0*RS + aC0*2, &g_h_lo[gA0 + aC0]);
        cpasync16(stu + 10240 + aR1*RS + aC1*2, &g_h_lo[gA1 + aC1]);
        CP_COMMIT();
        uint4 hv, lv;
        const float* p;
        p = wd + (size_t)bR0 * I_ + bC0;
        cvt8(*(const float4*)p, *(const float4*)(p + 4), hv, lv);
        *(uint4*)(st + 20480 + bR0*RS + bC0*2) = hv;
        *(uint4*)(st + 30720 + bR0*RS + bC0*2) = lv;
        p = wd + (size_t)bR1 * I_ + bC1;
        cvt8(*(const float4*)p, *(const float4*)(p + 4), hv, lv);
        *(uint4*)(st + 20480 + bR1*RS + bC1*2) = hv;
        *(uint4*)(st + 30720 + bR1*RS + bC1*2) = lv;
        CP_WAIT0();
    }
    __syncthreads();

    const int NK = I_ / KC;   // 24
    for (int k = 0; k < NK; k++) {
        int s = k & 1;
        bool pf = (k + 1 < NK);
        float4 pb0, pb1, pb2, pb3;
        if (pf) {
            int k0 = (k + 1) * KC;
            // kick A async copies for next stage immediately
            unsigned stu = sb + (s ^ 1) * DN_STAGE;
            cpasync16(stu + 0     + aR0*RS + aC0*2, &g_h_hi[gA0 + k0 + aC0]);
            cpasync16(stu + 0     + aR1*RS + aC1*2, &g_h_hi[gA1 + k0 + aC1]);
            cpasync16(stu + 10240 + aR0*RS + aC0*2, &g_h_lo[gA0 + k0 + aC0]);
            cpasync16(stu + 10240 + aR1*RS + aC1*2, &g_h_lo[gA1 + k0 + aC1]);
            CP_COMMIT();
            const float* p;
            p = wd + (size_t)bR0 * I_ + k0 + bC0; pb0 = *(const float4*)p; pb1 = *(const float4*)(p + 4);
            p = wd + (size_t)bR1 * I_ + k0 + bC1; pb2 = *(const float4*)p; pb3 = *(const float4*)(p + 4);
        }

        unsigned stb = sb + s * DN_STAGE;
#pragma unroll
        for (int kk = 0; kk < 2; kk++) {
            unsigned ah[2][4], al[2][4];
#pragma unroll
            for (int mt = 0; mt < 2; mt++) {
                unsigned arow = (unsigned)(wm*32 + mt*16 + (l & 15)) * RS;
                unsigned ak   = (unsigned)(kk*16 + ((l >> 4) << 3)) * 2;
                ldm4(ah[mt], stb + 0     + arow + ak);
                ldm4(al[mt], stb + 10240 + arow + ak);
            }
#pragma unroll
            for (int nt16 = 0; nt16 < 4; nt16++) {
                unsigned bro = (unsigned)(wn*64 + nt16*16 + ((l >> 4) & 1)*8 + (l & 7)) * RS
                             + (unsigned)(kk*16 + ((l >> 3) & 1)*8) * 2;
                unsigned bh[4], bl[4];
                ldm4(bh, stb + 20480 + bro);
                ldm4(bl, stb + 30720 + bro);
#pragma unroll
                for (int mt = 0; mt < 2; mt++) {
                    mma4(cd[mt][2*nt16],   ah[mt], bh);   mma4(cd[mt][2*nt16+1], ah[mt], bh+2);
                    mma4(cd[mt][2*nt16],   al[mt], bh);   mma4(cd[mt][2*nt16+1], al[mt], bh+2);
                    mma4(cd[mt][2*nt16],   ah[mt], bl);   mma4(cd[mt][2*nt16+1], ah[mt], bl+2);
                }
            }
        }

        if (pf) {
            char* st = smem + (s ^ 1) * DN_STAGE;
            uint4 hv, lv;
            cvt8(pb0, pb1, hv, lv);
            *(uint4*)(st + 20480 + bR0*RS + bC0*2) = hv;
            *(uint4*)(st + 30720 + bR0*RS + bC0*2) = lv;
            cvt8(pb2, pb3, hv, lv);
            *(uint4*)(st + 20480 + bR1*RS + bC1*2) = hv;
            *(uint4*)(st + 30720 + bR1*RS + bC1*2) = lv;
            CP_WAIT0();
        }
        __syncthreads();
    }

    // epilogue: scale by router weight, scatter rows of g_yp
#pragma unroll
    for (int mt = 0; mt < 2; mt++)
#pragma unroll
        for (int half = 0; half < 2; half++) {
            int rr = wm*32 + mt*16 + (l >> 2) + half*8;
            int pv = pvS[rr];
            if (pv >= 0) {
                float w = ew[pv];
                size_t base = (size_t)pv * H_ + col0 + wn*64 + (l & 3)*2;
#pragma unroll
                for (int nt = 0; nt < 8; nt++) {
                    float2 v = make_float2(w * cd[mt][nt][2*half], w * cd[mt][nt][2*half+1]);
                    *(float2*)(&g_yp[base + nt*8]) = v;
                }
            }
        }
}

// ---------------- combine ----------------
__global__ void k_combine(float* __restrict__ y) {
    int i = blockIdx.x * blockDim.x + threadIdx.x;
    if (i < T_ * H_ / 4) {
        int t  = i / (H_ / 4);
        int h4 = i - t * (H_ / 4);
        const float4* p = (const float4*)(&g_yp[(size_t)(t * K_) * H_]) + h4;
        float4 a = p[0];
        float4 b = p[H_ / 4];
        float4 c = p[2 * (H_ / 4)];
        float4 d = p[3 * (H_ / 4)];
        float4 o;
        o.x = a.x + b.x + c.x + d.x;
        o.y = a.y + b.y + c.y + d.y;
        o.z = a.z + b.z + c.z + d.z;
        o.w = a.w + b.w + c.w + d.w;
        ((float4*)y)[i] = o;
    }
}

// ---------------- launch ----------------
extern "C" void kernel_launch(void* const* d_in, const int* in_sizes, int n_in,
                              void* d_out, int out_size)
{
    const float* x   = (const float*)d_in[0];
    const float* Wg  = (const float*)d_in[1];
    const float* Wu  = (const float*)d_in[2];
    const float* Wd  = (const float*)d_in[3];
    const int*   ids = (const int*)d_in[4];
    const float* ew  = (const float*)d_in[5];
    float*       y   = (float*)d_out;

    cudaFuncSetAttribute(k_gateup_mma, cudaFuncAttributeMaxDynamicSharedMemorySize, GU_SMEM);
    cudaFuncSetAttribute(k_down_mma,   cudaFuncAttributeMaxDynamicSharedMemorySize, DN_SMEM);

    k_route<<<1, 1024>>>(ids);

    dim3 gA(I_ / 64, NA / 128, E_);    // (12, 32, 32)
    k_gateup_mma<<<gA, 256, GU_SMEM>>>(x, Wg, Wu);

    dim3 gB(H_ / 128, NA / 128, E_);   // (16, 32, 32)
    k_down_mma<<<gB, 256, DN_SMEM>>>(Wd, ew);

    k_combine<<<(T_ * H_ / 4 + 255) / 256, 256>>>(y);
}

// round 7
// speedup vs baseline: 1.1392x; 1.1392x over previous
#include <cuda_runtime.h>
#include <cuda_fp16.h>

// Problem constants
#define T_  1024
#define H_  2048
#define I_  768
#define E_  32
#define K_  4
#define NA  (T_*K_)   // 4096 assignment rows

#define KC  32
#define RS  80        // SMEM row stride bytes (32 fp16 + 16B pad) — conflict-free ldmatrix
#define WSCALE 1024.0f
#define WINV   (1.0f/1024.0f)

// ---------------- portable PTX helpers ----------------
__device__ __forceinline__ unsigned smem_u32(const void* p) {
    unsigned a;
    asm("{ .reg .u64 t; cvta.to.shared.u64 t, %1; cvt.u32.u64 %0, t; }" : "=r"(a) : "l"(p));
    return a;
}

__device__ __forceinline__ void ldm4(unsigned* d, unsigned a) {
    asm volatile("ldmatrix.sync.aligned.m8n8.x4.shared.b16 {%0,%1,%2,%3}, [%4];"
        : "=r"(d[0]), "=r"(d[1]), "=r"(d[2]), "=r"(d[3]) : "r"(a));
}

__device__ __forceinline__ void mma4(float* c, const unsigned* a, const unsigned* b) {
    asm volatile("mma.sync.aligned.m16n8k16.row.col.f32.f16.f16.f32 "
        "{%0,%1,%2,%3},{%4,%5,%6,%7},{%8,%9},{%0,%1,%2,%3};"
        : "+f"(c[0]), "+f"(c[1]), "+f"(c[2]), "+f"(c[3])
        : "r"(a[0]), "r"(a[1]), "r"(a[2]), "r"(a[3]), "r"(b[0]), "r"(b[1]));
}

__device__ __forceinline__ void cpasync16(unsigned saddr, const void* g) {
    asm volatile("cp.async.ca.shared.global [%0], [%1], 16;" :: "r"(saddr), "l"(g));
}
#define CP_COMMIT() asm volatile("cp.async.commit_group;")
#define CP_WAIT0()  asm volatile("cp.async.wait_group 0;")

// 8 fp32 -> 8 plain fp16 (activations)
__device__ __forceinline__ uint4 cvtA8(float4 a, float4 b) {
    float va[8] = {a.x, a.y, a.z, a.w, b.x, b.y, b.z, b.w};
    unsigned w[4];
#pragma unroll
    for (int j = 0; j < 4; j++) {
        __half2 h = __float22half2_rn(make_float2(va[2*j], va[2*j+1]));
        w[j] = *reinterpret_cast<unsigned*>(&h);
    }
    return make_uint4(w[0], w[1], w[2], w[3]);
}

// 8 fp32 weights -> scaled (x1024) fp16 hi + lo
__device__ __forceinline__ void cvtB8(float4 a, float4 b, uint4& hi, uint4& lo) {
    float va[8] = {a.x, a.y, a.z, a.w, b.x, b.y, b.z, b.w};
    unsigned hw[4], lw[4];
#pragma unroll
    for (int j = 0; j < 4; j++) {
        float2 f = make_float2(va[2*j] * WSCALE, va[2*j+1] * WSCALE);
        __half2 h = __float22half2_rn(f);
        float2 hf = __half22float2(h);
        __half2 l = __float22half2_rn(make_float2(f.x - hf.x, f.y - hf.y));
        hw[j] = *reinterpret_cast<unsigned*>(&h);
        lw[j] = *reinterpret_cast<unsigned*>(&l);
    }
    hi = make_uint4(hw[0], hw[1], hw[2], hw[3]);
    lo = make_uint4(lw[0], lw[1], lw[2], lw[3]);
}

// ---- device scratch ----
__device__ int   g_counts[E_];
__device__ int   g_offsets[E_];
__device__ int   g_perm[NA];
__device__ __align__(16) __half g_h[(size_t)NA * I_];
__device__ __align__(16) float  g_yp[(size_t)NA * H_];

// ---------------- routing ----------------
__global__ void k_route(const int* __restrict__ ids) {
    __shared__ int cnt[E_], offs[E_], cur[E_];
    int tid = threadIdx.x;   // 1024
    if (tid < E_) { cnt[tid] = 0; cur[tid] = 0; }
    __syncthreads();
    for (int i = tid; i < NA; i += 1024) atomicAdd(&cnt[ids[i]], 1);
    __syncthreads();
    if (tid == 0) {
        int acc = 0;
        for (int e = 0; e < E_; e++) {
            offs[e] = acc; g_offsets[e] = acc; g_counts[e] = cnt[e]; acc += cnt[e];
        }
    }
    __syncthreads();
    for (int i = tid; i < NA; i += 1024) {
        int e = ids[i];
        int p = atomicAdd(&cur[e], 1);
        g_perm[offs[e] + p] = i;
    }
}

// ---------------- gate+up mma GEMM: 64 x 128 tile ----------------
// Stage (46080 B): A 0 (5120), Bg_h 5120 (10240), Bg_l 15360,
// Bu_h 25600, Bu_l 35840. Double buffered.
#define GU_STAGE 46080
#define GU_SMEM  (2*GU_STAGE + 1024)
#define HST2     272     // epilogue staging row stride (128 fp16 + 16B pad)

__global__ void __launch_bounds__(256, 1) k_gateup_mma(
    const float* __restrict__ x,
    const float* __restrict__ Wg,
    const float* __restrict__ Wu)
{
    int e    = blockIdx.z;
    int cnt  = g_counts[e];
    int row0 = blockIdx.y * 64;
    if (row0 >= cnt) return;
    int off  = g_offsets[e];
    int col0 = blockIdx.x * 128;

    extern __shared__ char smem[];
    unsigned sb = smem_u32(smem);
    int tid = threadIdx.x;
    int wid = tid >> 5, l = tid & 31;
    int wm = wid & 1, wn = wid >> 1;   // 2 x 4 warp grid, warp tile 32x32

    int* toks = (int*)(smem + 2*GU_STAGE);
    if (tid < 64) {
        int r = row0 + tid;
        toks[tid] = g_perm[off + ((r < cnt) ? r : (cnt - 1))] >> 2;
    }
    __syncthreads();

    const float* wg = Wg + (size_t)e * I_ * H_ + (size_t)col0 * H_;
    const float* wu = Wu + (size_t)e * I_ * H_ + (size_t)col0 * H_;

    float cg[2][4][4], cu[2][4][4];
#pragma unroll
    for (int mt = 0; mt < 2; mt++)
#pragma unroll
        for (int nt = 0; nt < 4; nt++)
#pragma unroll
            for (int j = 0; j < 4; j++) { cg[mt][nt][j] = 0.f; cu[mt][nt][j] = 0.f; }

    int ar = tid >> 2, ac = (tid & 3) * 8;   // A: 64 rows x 32 fp32, 1 slot/thread

    // ---- prologue: chunk 0 -> stage 0 ----
    {
        char* st = smem;
        const float* p = x + (size_t)toks[ar] * H_ + ac;
        *(uint4*)(st + 0 + ar*RS + ac*2) = cvtA8(*(const float4*)p, *(const float4*)(p + 4));
        uint4 hv, lv;
#pragma unroll
        for (int i = 0; i < 2; i++) {
            int u = tid + 256*i, r = u >> 2, c = (u & 3) * 8;
            const float* pg = wg + (size_t)r * H_ + c;
            cvtB8(*(const float4*)pg, *(const float4*)(pg + 4), hv, lv);
            *(uint4*)(st + 5120  + r*RS + c*2) = hv;
            *(uint4*)(st + 15360 + r*RS + c*2) = lv;
            const float* pu = wu + (size_t)r * H_ + c;
            cvtB8(*(const float4*)pu, *(const float4*)(pu + 4), hv, lv);
            *(uint4*)(st + 25600 + r*RS + c*2) = hv;
            *(uint4*)(st + 35840 + r*RS + c*2) = lv;
        }
    }
    __syncthreads();

    const int NK = H_ / KC;   // 64
    for (int k = 0; k < NK; k++) {
        int s = k & 1;
        bool pf = (k + 1 < NK);
        float4 pa0, pa1, pg0, pg1, pg2, pg3, pu0, pu1, pu2, pu3;
        if (pf) {
            int k0 = (k + 1) * KC;
            const float* p;
            p = x + (size_t)toks[ar] * H_ + k0 + ac; pa0 = *(const float4*)p; pa1 = *(const float4*)(p + 4);
            int r0 = tid >> 2, c0 = (tid & 3) * 8;
            int u1i = tid + 256, r1 = u1i >> 2, c1 = (u1i & 3) * 8;
            p = wg + (size_t)r0 * H_ + k0 + c0; pg0 = *(const float4*)p; pg1 = *(const float4*)(p + 4);
            p = wg + (size_t)r1 * H_ + k0 + c1; pg2 = *(const float4*)p; pg3 = *(const float4*)(p + 4);
            p = wu + (size_t)r0 * H_ + k0 + c0; pu0 = *(const float4*)p; pu1 = *(const float4*)(p + 4);
            p = wu + (size_t)r1 * H_ + k0 + c1; pu2 = *(const float4*)p; pu3 = *(const float4*)(p + 4);
        }

        // ---- compute on stage s ----
        unsigned stb = sb + s * GU_STAGE;
#pragma unroll
        for (int kk = 0; kk < 2; kk++) {
            unsigned ah[2][4];
#pragma unroll
            for (int mt = 0; mt < 2; mt++) {
                unsigned arow = (unsigned)(wm*32 + mt*16 + (l & 15)) * RS;
                unsigned ak   = (unsigned)(kk*16 + ((l >> 4) << 3)) * 2;
                ldm4(ah[mt], stb + 0 + arow + ak);
            }
#pragma unroll
            for (int nt16 = 0; nt16 < 2; nt16++) {
                unsigned bro = (unsigned)(wn*32 + nt16*16 + ((l >> 4) & 1)*8 + (l & 7)) * RS
                             + (unsigned)(kk*16 + ((l >> 3) & 1)*8) * 2;
                unsigned bh[4], bl[4];
                ldm4(bh, stb + 5120  + bro);
                ldm4(bl, stb + 15360 + bro);
#pragma unroll
                for (int mt = 0; mt < 2; mt++) {
                    mma4(cg[mt][2*nt16],   ah[mt], bh);   mma4(cg[mt][2*nt16+1], ah[mt], bh+2);
                    mma4(cg[mt][2*nt16],   ah[mt], bl);   mma4(cg[mt][2*nt16+1], ah[mt], bl+2);
                }
                ldm4(bh, stb + 25600 + bro);
                ldm4(bl, stb + 35840 + bro);
#pragma unroll
                for (int mt = 0; mt < 2; mt++) {
                    mma4(cu[mt][2*nt16],   ah[mt], bh);   mma4(cu[mt][2*nt16+1], ah[mt], bh+2);
                    mma4(cu[mt][2*nt16],   ah[mt], bl);   mma4(cu[mt][2*nt16+1], ah[mt], bl+2);
                }
            }
        }

        if (pf) {
            char* st = smem + (s ^ 1) * GU_STAGE;
            *(uint4*)(st + 0 + ar*RS + ac*2) = cvtA8(pa0, pa1);
            int r0 = tid >> 2, c0 = (tid & 3) * 8;
            int u1i = tid + 256, r1 = u1i >> 2, c1 = (u1i & 3) * 8;
            uint4 hv, lv;
            cvtB8(pg0, pg1, hv, lv);
            *(uint4*)(st + 5120  + r0*RS + c0*2) = hv;
            *(uint4*)(st + 15360 + r0*RS + c0*2) = lv;
            cvtB8(pg2, pg3, hv, lv);
            *(uint4*)(st + 5120  + r1*RS + c1*2) = hv;
            *(uint4*)(st + 15360 + r1*RS + c1*2) = lv;
            cvtB8(pu0, pu1, hv, lv);
            *(uint4*)(st + 25600 + r0*RS + c0*2) = hv;
            *(uint4*)(st + 35840 + r0*RS + c0*2) = lv;
            cvtB8(pu2, pu3, hv, lv);
            *(uint4*)(st + 25600 + r1*RS + c1*2) = hv;
            *(uint4*)(st + 35840 + r1*RS + c1*2) = lv;
        }
        __syncthreads();
    }

    // ---- epilogue: h = silu(g/1024)*(u/1024) -> fp16, staged for coalescing ----
    char* sh = smem;   // 64 rows x HST2 = 17408 B
#pragma unroll
    for (int mt = 0; mt < 2; mt++)
#pragma unroll
        for (int nt = 0; nt < 4; nt++)
#pragma unroll
            for (int half = 0; half < 2; half++) {
                int rr = wm*32 + mt*16 + (l >> 2) + half*8;
                int cc = wn*32 + nt*8 + (l & 3)*2;
                float g0 = cg[mt][nt][2*half]   * WINV, g1 = cg[mt][nt][2*half+1] * WINV;
                float u0 = cu[mt][nt][2*half]   * WINV, u1 = cu[mt][nt][2*half+1] * WINV;
                float h0 = (g0 / (1.f + __expf(-g0))) * u0;
                float h1 = (g1 / (1.f + __expf(-g1))) * u1;
                __half2 hb = __float22half2_rn(make_float2(h0, h1));
                *(unsigned*)(sh + rr*HST2 + cc*2) = *reinterpret_cast<unsigned*>(&hb);
            }
    __syncthreads();
#pragma unroll
    for (int j = 0; j < 4; j++) {
        int u = tid + 256*j;           // 1024 slots: 64 rows x 16 uint4
        int r = u >> 4, c16 = u & 15;
        if (row0 + r < cnt) {
            size_t gidx = (size_t)(off + row0 + r) * I_ + col0 + c16*8;
            *(uint4*)&g_h[gidx] = *(uint4*)(sh + r*HST2 + c16*16);
        }
    }
}

// ---------------- down mma GEMM: 64 x 128 tile ----------------
// Stage (25600): A 0 (5120), B_h 5120 (10240), B_l 15360 (10240).
#define DN_STAGE 25600
#define DN_SMEM  (2*DN_STAGE + 1024)

__global__ void __launch_bounds__(256, 2) k_down_mma(
    const float* __restrict__ Wd,
    const float* __restrict__ ew)
{
    int e    = blockIdx.z;
    int cnt  = g_counts[e];
    int row0 = blockIdx.y * 64;
    if (row0 >= cnt) return;
    int off  = g_offsets[e];
    int col0 = blockIdx.x * 128;

    extern __shared__ char smem[];
    unsigned sb = smem_u32(smem);
    int tid = threadIdx.x;
    int wid = tid >> 5, l = tid & 31;
    int wm = wid & 1, wn = wid >> 1;   // 2 x 4, warp tile 32 x 32

    int* pvS = (int*)(smem + 2*DN_STAGE);
    if (tid < 64) {
        int r = row0 + tid;
        pvS[tid] = (r < cnt) ? g_perm[off + r] : -1;
    }
    __syncthreads();

    const float* wd = Wd + (size_t)e * H_ * I_ + (size_t)col0 * I_;

    float cd[2][4][4];
#pragma unroll
    for (int mt = 0; mt < 2; mt++)
#pragma unroll
        for (int nt = 0; nt < 4; nt++)
#pragma unroll
            for (int j = 0; j < 4; j++) cd[mt][nt][j] = 0.f;

    // A via cp.async: 64 rows x 32 fp16 (64 B/row), 1 slot (16 B)/thread
    int aR = tid >> 2, aC = (tid & 3) * 8;
    int rrA = row0 + aR;
    size_t gA = (size_t)(off + ((rrA < cnt) ? rrA : (cnt - 1))) * I_;
    // B: 128 rows x 32 fp32, 2 slots/thread
    int bR0 = tid >> 2,         bC0 = (tid & 3) * 8;
    int bR1 = (tid + 256) >> 2, bC1 = (tid & 3) * 8;

    // prologue: chunk 0 -> stage 0
    {
        char* st = smem;
        cpasync16(sb + 0 + aR*RS + aC*2, &g_h[gA + aC]);
        CP_COMMIT();
        uint4 hv, lv;
        const float* p;
        p = wd + (size_t)bR0 * I_ + bC0;
        cvtB8(*(const float4*)p, *(const float4*)(p + 4), hv, lv);
        *(uint4*)(st + 5120  + bR0*RS + bC0*2) = hv;
        *(uint4*)(st + 15360 + bR0*RS + bC0*2) = lv;
        p = wd + (size_t)bR1 * I_ + bC1;
        cvtB8(*(const float4*)p, *(const float4*)(p + 4), hv, lv);
        *(uint4*)(st + 5120  + bR1*RS + bC1*2) = hv;
        *(uint4*)(st + 15360 + bR1*RS + bC1*2) = lv;
        CP_WAIT0();
    }
    __syncthreads();

    const int NK = I_ / KC;   // 24
    for (int k = 0; k < NK; k++) {
        int s = k & 1;
        bool pf = (k + 1 < NK);
        float4 pb0, pb1, pb2, pb3;
        if (pf) {
            int k0 = (k + 1) * KC;
            cpasync16(sb + (s ^ 1) * DN_STAGE + 0 + aR*RS + aC*2, &g_h[gA + k0 + aC]);
            CP_COMMIT();
            const float* p;
            p = wd + (size_t)bR0 * I_ + k0 + bC0; pb0 = *(const float4*)p; pb1 = *(const float4*)(p + 4);
            p = wd + (size_t)bR1 * I_ + k0 + bC1; pb2 = *(const float4*)p; pb3 = *(const float4*)(p + 4);
        }

        unsigned stb = sb + s * DN_STAGE;
#pragma unroll
        for (int kk = 0; kk < 2; kk++) {
            unsigned ah[2][4];
#pragma unroll
            for (int mt = 0; mt < 2; mt++) {
                unsigned arow = (unsigned)(wm*32 + mt*16 + (l & 15)) * RS;
                unsigned ak   = (unsigned)(kk*16 + ((l >> 4) << 3)) * 2;
                ldm4(ah[mt], stb + 0 + arow + ak);
            }
#pragma unroll
            for (int nt16 = 0; nt16 < 2; nt16++) {
                unsigned bro = (unsigned)(wn*32 + nt16*16 + ((l >> 4) & 1)*8 + (l & 7)) * RS
                             + (unsigned)(kk*16 + ((l >> 3) & 1)*8) * 2;
                unsigned bh[4], bl[4];
                ldm4(bh, stb + 5120  + bro);
                ldm4(bl, stb + 15360 + bro);
#pragma unroll
                for (int mt = 0; mt < 2; mt++) {
                    mma4(cd[mt][2*nt16],   ah[mt], bh);   mma4(cd[mt][2*nt16+1], ah[mt], bh+2);
                    mma4(cd[mt][2*nt16],   ah[mt], bl);   mma4(cd[mt][2*nt16+1], ah[mt], bl+2);
                }
            }
        }

        if (pf) {
            char* st = smem + (s ^ 1) * DN_STAGE;
            uint4 hv, lv;
            cvtB8(pb0, pb1, hv, lv);
            *(uint4*)(st + 5120  + bR0*RS + bC0*2) = hv;
            *(uint4*)(st + 15360 + bR0*RS + bC0*2) = lv;
            cvtB8(pb2, pb3, hv, lv);
            *(uint4*)(st + 5120  + bR1*RS + bC1*2) = hv;
            *(uint4*)(st + 15360 + bR1*RS + bC1*2) = lv;
            CP_WAIT0();
        }
        __syncthreads();
    }

    // epilogue: scale by router weight / 1024, scatter rows of g_yp
#pragma unroll
    for (int mt = 0; mt < 2; mt++)
#pragma unroll
        for (int half = 0; half < 2; half++) {
            int rr = wm*32 + mt*16 + (l >> 2) + half*8;
            int pv = pvS[rr];
            if (pv >= 0) {
                float w = ew[pv] * WINV;
                size_t base = (size_t)pv * H_ + col0 + wn*32 + (l & 3)*2;
#pragma unroll
                for (int nt = 0; nt < 4; nt++) {
                    float2 v = make_float2(w * cd[mt][nt][2*half], w * cd[mt][nt][2*half+1]);
                    *(float2*)(&g_yp[base + nt*8]) = v;
                }
            }
        }
}

// ---------------- combine ----------------
__global__ void k_combine(float* __restrict__ y) {
    int i = blockIdx.x * blockDim.x + threadIdx.x;
    if (i < T_ * H_ / 4) {
        int t  = i / (H_ / 4);
        int h4 = i - t * (H_ / 4);
        const float4* p = (const float4*)(&g_yp[(size_t)(t * K_) * H_]) + h4;
        float4 a = p[0];
        float4 b = p[H_ / 4];
        float4 c = p[2 * (H_ / 4)];
        float4 d = p[3 * (H_ / 4)];
        float4 o;
        o.x = a.x + b.x + c.x + d.x;
        o.y = a.y + b.y + c.y + d.y;
        o.z = a.z + b.z + c.z + d.z;
        o.w = a.w + b.w + c.w + d.w;
        ((float4*)y)[i] = o;
    }
}

// ---------------- launch ----------------
extern "C" void kernel_launch(void* const* d_in, const int* in_sizes, int n_in,
                              void* d_out, int out_size)
{
    const float* x   = (const float*)d_in[0];
    const float* Wg  = (const float*)d_in[1];
    const float* Wu  = (const float*)d_in[2];
    const float* Wd  = (const float*)d_in[3];
    const int*   ids = (const int*)d_in[4];
    const float* ew  = (const float*)d_in[5];
    float*       y   = (float*)d_out;

    cudaFuncSetAttribute(k_gateup_mma, cudaFuncAttributeMaxDynamicSharedMemorySize, GU_SMEM);
    cudaFuncSetAttribute(k_down_mma,   cudaFuncAttributeMaxDynamicSharedMemorySize, DN_SMEM);

    k_route<<<1, 1024>>>(ids);

    dim3 gA(I_ / 128, NA / 64, E_);    // (6, 64, 32)
    k_gateup_mma<<<gA, 256, GU_SMEM>>>(x, Wg, Wu);

    dim3 gB(H_ / 128, NA / 64, E_);    // (16, 64, 32)
    k_down_mma<<<gB, 256, DN_SMEM>>>(Wd, ew);

    k_combine<<<(T_ * H_ / 4 + 255) / 256, 256>>>(y);
}

// round 8
// speedup vs baseline: 1.2023x; 1.0554x over previous
#include <cuda_runtime.h>
#include <cuda_fp16.h>

// Problem constants
#define T_  1024
#define H_  2048
#define I_  768
#define E_  32
#define K_  4
#define NA  (T_*K_)   // 4096 assignment rows

#define KC  32
#define RS  80        // SMEM row stride bytes (32 fp16 + 16B pad) — conflict-free ldmatrix
#define WSCALE 1024.0f
#define WINV   (1.0f/1024.0f)

// ---------------- portable PTX helpers ----------------
__device__ __forceinline__ unsigned smem_u32(const void* p) {
    unsigned a;
    asm("{ .reg .u64 t; cvta.to.shared.u64 t, %1; cvt.u32.u64 %0, t; }" : "=r"(a) : "l"(p));
    return a;
}

__device__ __forceinline__ void ldm4(unsigned* d, unsigned a) {
    asm volatile("ldmatrix.sync.aligned.m8n8.x4.shared.b16 {%0,%1,%2,%3}, [%4];"
        : "=r"(d[0]), "=r"(d[1]), "=r"(d[2]), "=r"(d[3]) : "r"(a));
}

__device__ __forceinline__ void mma4(float* c, const unsigned* a, const unsigned* b) {
    asm volatile("mma.sync.aligned.m16n8k16.row.col.f32.f16.f16.f32 "
        "{%0,%1,%2,%3},{%4,%5,%6,%7},{%8,%9},{%0,%1,%2,%3};"
        : "+f"(c[0]), "+f"(c[1]), "+f"(c[2]), "+f"(c[3])
        : "r"(a[0]), "r"(a[1]), "r"(a[2]), "r"(a[3]), "r"(b[0]), "r"(b[1]));
}

__device__ __forceinline__ void cpasync16(unsigned saddr, const void* g) {
    asm volatile("cp.async.ca.shared.global [%0], [%1], 16;" :: "r"(saddr), "l"(g));
}
#define CP_COMMIT() asm volatile("cp.async.commit_group;")
#define CP_WAIT0()  asm volatile("cp.async.wait_group 0;")

// 8 fp32 -> 8 plain fp16 (activations)
__device__ __forceinline__ uint4 cvtA8(float4 a, float4 b) {
    float va[8] = {a.x, a.y, a.z, a.w, b.x, b.y, b.z, b.w};
    unsigned w[4];
#pragma unroll
    for (int j = 0; j < 4; j++) {
        __half2 h = __float22half2_rn(make_float2(va[2*j], va[2*j+1]));
        w[j] = *reinterpret_cast<unsigned*>(&h);
    }
    return make_uint4(w[0], w[1], w[2], w[3]);
}

// 8 fp32 weights -> scaled (x1024) fp16 hi + lo
__device__ __forceinline__ void cvtB8(float4 a, float4 b, uint4& hi, uint4& lo) {
    float va[8] = {a.x, a.y, a.z, a.w, b.x, b.y, b.z, b.w};
    unsigned hw[4], lw[4];
#pragma unroll
    for (int j = 0; j < 4; j++) {
        float2 f = make_float2(va[2*j] * WSCALE, va[2*j+1] * WSCALE);
        __half2 h = __float22half2_rn(f);
        float2 hf = __half22float2(h);
        __half2 l = __float22half2_rn(make_float2(f.x - hf.x, f.y - hf.y));
        hw[j] = *reinterpret_cast<unsigned*>(&h);
        lw[j] = *reinterpret_cast<unsigned*>(&l);
    }
    hi = make_uint4(hw[0], hw[1], hw[2], hw[3]);
    lo = make_uint4(lw[0], lw[1], lw[2], lw[3]);
}

// ---- device scratch ----
__device__ int   g_counts[E_];
__device__ int   g_offsets[E_];
__device__ int   g_perm[NA];
__device__ __align__(16) __half g_h[(size_t)NA * I_];
__device__ __align__(16) float  g_yp[(size_t)NA * H_];

// ---------------- routing ----------------
__global__ void k_route(const int* __restrict__ ids) {
    __shared__ int cnt[E_], offs[E_], cur[E_];
    int tid = threadIdx.x;   // 1024
    if (tid < E_) { cnt[tid] = 0; cur[tid] = 0; }
    __syncthreads();
    for (int i = tid; i < NA; i += 1024) atomicAdd(&cnt[ids[i]], 1);
    __syncthreads();
    if (tid == 0) {
        int acc = 0;
        for (int e = 0; e < E_; e++) {
            offs[e] = acc; g_offsets[e] = acc; g_counts[e] = cnt[e]; acc += cnt[e];
        }
    }
    __syncthreads();
    for (int i = tid; i < NA; i += 1024) {
        int e = ids[i];
        int p = atomicAdd(&cur[e], 1);
        g_perm[offs[e] + p] = i;
    }
}

// ---------------- gate+up mma GEMM: 64 x 64 tile, 2 CTA/SM ----------------
// Stage (25600 B): A 0 (5120), Bg_h 5120, Bg_l 10240, Bu_h 15360, Bu_l 20480.
#define GU_STAGE 25600
#define GU_SMEM  (2*GU_STAGE + 1024)
#define HST2     144     // epilogue staging row stride (64 fp16 + 16B pad)

__global__ void __launch_bounds__(256, 2) k_gateup_mma(
    const float* __restrict__ x,
    const float* __restrict__ Wg,
    const float* __restrict__ Wu)
{
    int e    = blockIdx.z;
    int cnt  = g_counts[e];
    int row0 = blockIdx.y * 64;
    if (row0 >= cnt) return;
    int off  = g_offsets[e];
    int col0 = blockIdx.x * 64;

    extern __shared__ char smem[];
    unsigned sb = smem_u32(smem);
    int tid = threadIdx.x;
    int wid = tid >> 5, l = tid & 31;
    int wm = wid & 1, wn = wid >> 1;   // 2 x 4 warp grid, warp tile 32 x 16

    int* toks = (int*)(smem + 2*GU_STAGE);
    if (tid < 64) {
        int r = row0 + tid;
        toks[tid] = g_perm[off + ((r < cnt) ? r : (cnt - 1))] >> 2;
    }
    __syncthreads();

    const float* wg = Wg + (size_t)e * I_ * H_ + (size_t)col0 * H_;
    const float* wu = Wu + (size_t)e * I_ * H_ + (size_t)col0 * H_;

    float cg[2][2][4], cu[2][2][4];
#pragma unroll
    for (int mt = 0; mt < 2; mt++)
#pragma unroll
        for (int nt = 0; nt < 2; nt++)
#pragma unroll
            for (int j = 0; j < 4; j++) { cg[mt][nt][j] = 0.f; cu[mt][nt][j] = 0.f; }

    int ar = tid >> 2, ac = (tid & 3) * 8;   // A/B fill: 64 rows x 32 fp32, 1 slot/thread

    // ---- prologue: chunk 0 -> stage 0 ----
    {
        char* st = smem;
        const float* p = x + (size_t)toks[ar] * H_ + ac;
        *(uint4*)(st + 0 + ar*RS + ac*2) = cvtA8(*(const float4*)p, *(const float4*)(p + 4));
        uint4 hv, lv;
        const float* pg = wg + (size_t)ar * H_ + ac;
        cvtB8(*(const float4*)pg, *(const float4*)(pg + 4), hv, lv);
        *(uint4*)(st + 5120  + ar*RS + ac*2) = hv;
        *(uint4*)(st + 10240 + ar*RS + ac*2) = lv;
        const float* pu = wu + (size_t)ar * H_ + ac;
        cvtB8(*(const float4*)pu, *(const float4*)(pu + 4), hv, lv);
        *(uint4*)(st + 15360 + ar*RS + ac*2) = hv;
        *(uint4*)(st + 20480 + ar*RS + ac*2) = lv;
    }
    __syncthreads();

    const int NK = H_ / KC;   // 64
    for (int k = 0; k < NK; k++) {
        int s = k & 1;
        bool pf = (k + 1 < NK);
        float4 pa0, pa1, pg0, pg1, pu0, pu1;
        if (pf) {
            int k0 = (k + 1) * KC;
            const float* p;
            p = x + (size_t)toks[ar] * H_ + k0 + ac;  pa0 = *(const float4*)p; pa1 = *(const float4*)(p + 4);
            p = wg + (size_t)ar * H_ + k0 + ac;       pg0 = *(const float4*)p; pg1 = *(const float4*)(p + 4);
            p = wu + (size_t)ar * H_ + k0 + ac;       pu0 = *(const float4*)p; pu1 = *(const float4*)(p + 4);
        }

        // ---- compute on stage s ----
        unsigned stb = sb + s * GU_STAGE;
#pragma unroll
        for (int kk = 0; kk < 2; kk++) {
            unsigned ah[2][4];
#pragma unroll
            for (int mt = 0; mt < 2; mt++) {
                unsigned arow = (unsigned)(wm*32 + mt*16 + (l & 15)) * RS;
                unsigned ak   = (unsigned)(kk*16 + ((l >> 4) << 3)) * 2;
                ldm4(ah[mt], stb + 0 + arow + ak);
            }
            unsigned bro = (unsigned)(wn*16 + ((l >> 4) & 1)*8 + (l & 7)) * RS
                         + (unsigned)(kk*16 + ((l >> 3) & 1)*8) * 2;
            unsigned bh[4], bl[4];
            ldm4(bh, stb + 5120  + bro);
            ldm4(bl, stb + 10240 + bro);
#pragma unroll
            for (int mt = 0; mt < 2; mt++) {
                mma4(cg[mt][0], ah[mt], bh);   mma4(cg[mt][1], ah[mt], bh+2);
                mma4(cg[mt][0], ah[mt], bl);   mma4(cg[mt][1], ah[mt], bl+2);
            }
            ldm4(bh, stb + 15360 + bro);
            ldm4(bl, stb + 20480 + bro);
#pragma unroll
            for (int mt = 0; mt < 2; mt++) {
                mma4(cu[mt][0], ah[mt], bh);   mma4(cu[mt][1], ah[mt], bh+2);
                mma4(cu[mt][0], ah[mt], bl);   mma4(cu[mt][1], ah[mt], bl+2);
            }
        }

        if (pf) {
            char* st = smem + (s ^ 1) * GU_STAGE;
            *(uint4*)(st + 0 + ar*RS + ac*2) = cvtA8(pa0, pa1);
            uint4 hv, lv;
            cvtB8(pg0, pg1, hv, lv);
            *(uint4*)(st + 5120  + ar*RS + ac*2) = hv;
            *(uint4*)(st + 10240 + ar*RS + ac*2) = lv;
            cvtB8(pu0, pu1, hv, lv);
            *(uint4*)(st + 15360 + ar*RS + ac*2) = hv;
            *(uint4*)(st + 20480 + ar*RS + ac*2) = lv;
        }
        __syncthreads();
    }

    // ---- epilogue: h = silu(g/1024)*(u/1024) -> fp16, staged for coalescing ----
    char* sh = smem;   // 64 rows x HST2 = 9216 B
#pragma unroll
    for (int mt = 0; mt < 2; mt++)
#pragma unroll
        for (int nt = 0; nt < 2; nt++)
#pragma unroll
            for (int half = 0; half < 2; half++) {
                int rr = wm*32 + mt*16 + (l >> 2) + half*8;
                int cc = wn*16 + nt*8 + (l & 3)*2;
                float g0 = cg[mt][nt][2*half]   * WINV, g1 = cg[mt][nt][2*half+1] * WINV;
                float u0 = cu[mt][nt][2*half]   * WINV, u1 = cu[mt][nt][2*half+1] * WINV;
                float h0 = (g0 / (1.f + __expf(-g0))) * u0;
                float h1 = (g1 / (1.f + __expf(-g1))) * u1;
                __half2 hb = __float22half2_rn(make_float2(h0, h1));
                *(unsigned*)(sh + rr*HST2 + cc*2) = *reinterpret_cast<unsigned*>(&hb);
            }
    __syncthreads();
#pragma unroll
    for (int j = 0; j < 2; j++) {
        int u = tid + 256*j;           // 512 slots: 64 rows x 8 uint4
        int r = u >> 3, c8 = u & 7;
        if (row0 + r < cnt) {
            size_t gidx = (size_t)(off + row0 + r) * I_ + col0 + c8*8;
            *(uint4*)&g_h[gidx] = *(uint4*)(sh + r*HST2 + c8*16);
        }
    }
}

// ---------------- down mma GEMM: 64 x 128 tile ----------------
// Stage (25600): A 0 (5120), B_h 5120 (10240), B_l 15360 (10240).
#define DN_STAGE 25600
#define DN_SMEM  (2*DN_STAGE + 1024)

__global__ void __launch_bounds__(256, 2) k_down_mma(
    const float* __restrict__ Wd,
    const float* __restrict__ ew)
{
    int e    = blockIdx.z;
    int cnt  = g_counts[e];
    int row0 = blockIdx.y * 64;
    if (row0 >= cnt) return;
    int off  = g_offsets[e];
    int col0 = blockIdx.x * 128;

    extern __shared__ char smem[];
    unsigned sb = smem_u32(smem);
    int tid = threadIdx.x;
    int wid = tid >> 5, l = tid & 31;
    int wm = wid & 1, wn = wid >> 1;   // 2 x 4, warp tile 32 x 32

    int* pvS = (int*)(smem + 2*DN_STAGE);
    if (tid < 64) {
        int r = row0 + tid;
        pvS[tid] = (r < cnt) ? g_perm[off + r] : -1;
    }
    __syncthreads();

    const float* wd = Wd + (size_t)e * H_ * I_ + (size_t)col0 * I_;

    float cd[2][4][4];
#pragma unroll
    for (int mt = 0; mt < 2; mt++)
#pragma unroll
        for (int nt = 0; nt < 4; nt++)
#pragma unroll
            for (int j = 0; j < 4; j++) cd[mt][nt][j] = 0.f;

    // A via cp.async: 64 rows x 32 fp16 (64 B/row), 1 slot (16 B)/thread
    int aR = tid >> 2, aC = (tid & 3) * 8;
    int rrA = row0 + aR;
    size_t gA = (size_t)(off + ((rrA < cnt) ? rrA : (cnt - 1))) * I_;
    // B: 128 rows x 32 fp32, 2 slots/thread
    int bR0 = tid >> 2,         bC0 = (tid & 3) * 8;
    int bR1 = (tid + 256) >> 2, bC1 = (tid & 3) * 8;

    // prologue: chunk 0 -> stage 0
    {
        char* st = smem;
        cpasync16(sb + 0 + aR*RS + aC*2, &g_h[gA + aC]);
        CP_COMMIT();
        uint4 hv, lv;
        const float* p;
        p = wd + (size_t)bR0 * I_ + bC0;
        cvtB8(*(const float4*)p, *(const float4*)(p + 4), hv, lv);
        *(uint4*)(st + 5120  + bR0*RS + bC0*2) = hv;
        *(uint4*)(st + 15360 + bR0*RS + bC0*2) = lv;
        p = wd + (size_t)bR1 * I_ + bC1;
        cvtB8(*(const float4*)p, *(const float4*)(p + 4), hv, lv);
        *(uint4*)(st + 5120  + bR1*RS + bC1*2) = hv;
        *(uint4*)(st + 15360 + bR1*RS + bC1*2) = lv;
        CP_WAIT0();
    }
    __syncthreads();

    const int NK = I_ / KC;   // 24
    for (int k = 0; k < NK; k++) {
        int s = k & 1;
        bool pf = (k + 1 < NK);
        float4 pb0, pb1, pb2, pb3;
        if (pf) {
            int k0 = (k + 1) * KC;
            cpasync16(sb + (s ^ 1) * DN_STAGE + 0 + aR*RS + aC*2, &g_h[gA + k0 + aC]);
            CP_COMMIT();
            const float* p;
            p = wd + (size_t)bR0 * I_ + k0 + bC0; pb0 = *(const float4*)p; pb1 = *(const float4*)(p + 4);
            p = wd + (size_t)bR1 * I_ + k0 + bC1; pb2 = *(const float4*)p; pb3 = *(const float4*)(p + 4);
        }

        unsigned stb = sb + s * DN_STAGE;
#pragma unroll
        for (int kk = 0; kk < 2; kk++) {
            unsigned ah[2][4];
#pragma unroll
            for (int mt = 0; mt < 2; mt++) {
                unsigned arow = (unsigned)(wm*32 + mt*16 + (l & 15)) * RS;
                unsigned ak   = (unsigned)(kk*16 + ((l >> 4) << 3)) * 2;
                ldm4(ah[mt], stb + 0 + arow + ak);
            }
#pragma unroll
            for (int nt16 = 0; nt16 < 2; nt16++) {
                unsigned bro = (unsigned)(wn*32 + nt16*16 + ((l >> 4) & 1)*8 + (l & 7)) * RS
                             + (unsigned)(kk*16 + ((l >> 3) & 1)*8) * 2;
                unsigned bh[4], bl[4];
                ldm4(bh, stb + 5120  + bro);
                ldm4(bl, stb + 15360 + bro);
#pragma unroll
                for (int mt = 0; mt < 2; mt++) {
                    mma4(cd[mt][2*nt16],   ah[mt], bh);   mma4(cd[mt][2*nt16+1], ah[mt], bh+2);
                    mma4(cd[mt][2*nt16],   ah[mt], bl);   mma4(cd[mt][2*nt16+1], ah[mt], bl+2);
                }
            }
        }

        if (pf) {
            char* st = smem + (s ^ 1) * DN_STAGE;
            uint4 hv, lv;
            cvtB8(pb0, pb1, hv, lv);
            *(uint4*)(st + 5120  + bR0*RS + bC0*2) = hv;
            *(uint4*)(st + 15360 + bR0*RS + bC0*2) = lv;
            cvtB8(pb2, pb3, hv, lv);
            *(uint4*)(st + 5120  + bR1*RS + bC1*2) = hv;
            *(uint4*)(st + 15360 + bR1*RS + bC1*2) = lv;
            CP_WAIT0();
        }
        __syncthreads();
    }

    // epilogue: scale by router weight / 1024, scatter rows of g_yp
#pragma unroll
    for (int mt = 0; mt < 2; mt++)
#pragma unroll
        for (int half = 0; half < 2; half++) {
            int rr = wm*32 + mt*16 + (l >> 2) + half*8;
            int pv = pvS[rr];
            if (pv >= 0) {
                float w = ew[pv] * WINV;
                size_t base = (size_t)pv * H_ + col0 + wn*32 + (l & 3)*2;
#pragma unroll
                for (int nt = 0; nt < 4; nt++) {
                    float2 v = make_float2(w * cd[mt][nt][2*half], w * cd[mt][nt][2*half+1]);
                    *(float2*)(&g_yp[base + nt*8]) = v;
                }
            }
        }
}

// ---------------- combine ----------------
__global__ void k_combine(float* __restrict__ y) {
    int i = blockIdx.x * blockDim.x + threadIdx.x;
    if (i < T_ * H_ / 4) {
        int t  = i / (H_ / 4);
        int h4 = i - t * (H_ / 4);
        const float4* p = (const float4*)(&g_yp[(size_t)(t * K_) * H_]) + h4;
        float4 a = p[0];
        float4 b = p[H_ / 4];
        float4 c = p[2 * (H_ / 4)];
        float4 d = p[3 * (H_ / 4)];
        float4 o;
        o.x = a.x + b.x + c.x + d.x;
        o.y = a.y + b.y + c.y + d.y;
        o.z = a.z + b.z + c.z + d.z;
        o.w = a.w + b.w + c.w + d.w;
        ((float4*)y)[i] = o;
    }
}

// ---------------- launch ----------------
extern "C" void kernel_launch(void* const* d_in, const int* in_sizes, int n_in,
                              void* d_out, int out_size)
{
    const float* x   = (const float*)d_in[0];
    const float* Wg  = (const float*)d_in[1];
    const float* Wu  = (const float*)d_in[2];
    const float* Wd  = (const float*)d_in[3];
    const int*   ids = (const int*)d_in[4];
    const float* ew  = (const float*)d_in[5];
    float*       y   = (float*)d_out;

    cudaFuncSetAttribute(k_gateup_mma, cudaFuncAttributeMaxDynamicSharedMemorySize, GU_SMEM);
    cudaFuncSetAttribute(k_down_mma,   cudaFuncAttributeMaxDynamicSharedMemorySize, DN_SMEM);

    k_route<<<1, 1024>>>(ids);

    dim3 gA(I_ / 64, NA / 64, E_);     // (12, 64, 32)
    k_gateup_mma<<<gA, 256, GU_SMEM>>>(x, Wg, Wu);

    dim3 gB(H_ / 128, NA / 64, E_);    // (16, 64, 32)
    k_down_mma<<<gB, 256, DN_SMEM>>>(Wd, ew);

    k_combine<<<(T_ * H_ / 4 + 255) / 256, 256>>>(y);
}

// round 9
// speedup vs baseline: 1.2370x; 1.0289x over previous
#include <cuda_runtime.h>
#include <cuda_fp16.h>

// Problem constants
#define T_  1024
#define H_  2048
#define I_  768
#define E_  32
#define K_  4
#define NA  (T_*K_)   // 4096 assignment rows

#define KC  32
#define RS  80        // SMEM row stride bytes (32 fp16 + 16B pad) — conflict-free ldmatrix
#define WSCALE 1024.0f
#define WINV   (1.0f/1024.0f)
#define NPERS 304     // persistent CTAs (2/SM)

// ---------------- portable PTX helpers ----------------
__device__ __forceinline__ unsigned smem_u32(const void* p) {
    unsigned a;
    asm("{ .reg .u64 t; cvta.to.shared.u64 t, %1; cvt.u32.u64 %0, t; }" : "=r"(a) : "l"(p));
    return a;
}

__device__ __forceinline__ void ldm4(unsigned* d, unsigned a) {
    asm volatile("ldmatrix.sync.aligned.m8n8.x4.shared.b16 {%0,%1,%2,%3}, [%4];"
        : "=r"(d[0]), "=r"(d[1]), "=r"(d[2]), "=r"(d[3]) : "r"(a));
}

__device__ __forceinline__ void mma4(float* c, const unsigned* a, const unsigned* b) {
    asm volatile("mma.sync.aligned.m16n8k16.row.col.f32.f16.f16.f32 "
        "{%0,%1,%2,%3},{%4,%5,%6,%7},{%8,%9},{%0,%1,%2,%3};"
        : "+f"(c[0]), "+f"(c[1]), "+f"(c[2]), "+f"(c[3])
        : "r"(a[0]), "r"(a[1]), "r"(a[2]), "r"(a[3]), "r"(b[0]), "r"(b[1]));
}

__device__ __forceinline__ void cpasync16(unsigned saddr, const void* g) {
    asm volatile("cp.async.ca.shared.global [%0], [%1], 16;" :: "r"(saddr), "l"(g));
}
#define CP_COMMIT() asm volatile("cp.async.commit_group;")
#define CP_WAIT0()  asm volatile("cp.async.wait_group 0;")

// 8 fp32 -> 8 plain fp16 (activations)
__device__ __forceinline__ uint4 cvtA8(float4 a, float4 b) {
    float va[8] = {a.x, a.y, a.z, a.w, b.x, b.y, b.z, b.w};
    unsigned w[4];
#pragma unroll
    for (int j = 0; j < 4; j++) {
        __half2 h = __float22half2_rn(make_float2(va[2*j], va[2*j+1]));
        w[j] = *reinterpret_cast<unsigned*>(&h);
    }
    return make_uint4(w[0], w[1], w[2], w[3]);
}

// 8 fp32 weights -> scaled (x1024) fp16 hi + lo
__device__ __forceinline__ void cvtB8(float4 a, float4 b, uint4& hi, uint4& lo) {
    float va[8] = {a.x, a.y, a.z, a.w, b.x, b.y, b.z, b.w};
    unsigned hw[4], lw[4];
#pragma unroll
    for (int j = 0; j < 4; j++) {
        float2 f = make_float2(va[2*j] * WSCALE, va[2*j+1] * WSCALE);
        __half2 h = __float22half2_rn(f);
        float2 hf = __half22float2(h);
        __half2 l = __float22half2_rn(make_float2(f.x - hf.x, f.y - hf.y));
        hw[j] = *reinterpret_cast<unsigned*>(&h);
        lw[j] = *reinterpret_cast<unsigned*>(&l);
    }
    hi = make_uint4(hw[0], hw[1], hw[2], hw[3]);
    lo = make_uint4(lw[0], lw[1], lw[2], lw[3]);
}

// ---- device scratch ----
__device__ int   g_counts[E_];
__device__ int   g_offsets[E_];
__device__ int   g_perm[NA];
__device__ int   g_nrt;
__device__ int   g_rt_e[160];
__device__ int   g_rt_r0[160];
__device__ int   g_tick[2];
__device__ __align__(16) __half g_h[(size_t)NA * I_];
__device__ __align__(16) float  g_yp[(size_t)NA * H_];

// ---------------- routing + tile list ----------------
__global__ void k_route(const int* __restrict__ ids) {
    __shared__ int cnt[E_], offs[E_], cur[E_];
    int tid = threadIdx.x;   // 1024
    if (tid < E_) { cnt[tid] = 0; cur[tid] = 0; }
    __syncthreads();
    for (int i = tid; i < NA; i += 1024) atomicAdd(&cnt[ids[i]], 1);
    __syncthreads();
    if (tid == 0) {
        int acc = 0, n = 0;
        for (int e = 0; e < E_; e++) {
            offs[e] = acc; g_offsets[e] = acc; g_counts[e] = cnt[e]; acc += cnt[e];
            for (int r0 = 0; r0 < cnt[e]; r0 += 64) { g_rt_e[n] = e; g_rt_r0[n] = r0; n++; }
        }
        g_nrt = n;
        g_tick[0] = 0; g_tick[1] = 0;
    }
    __syncthreads();
    for (int i = tid; i < NA; i += 1024) {
        int e = ids[i];
        int p = atomicAdd(&cur[e], 1);
        g_perm[offs[e] + p] = i;
    }
}

// ---------------- gate+up mma GEMM: persistent, 64 x 64 tiles ----------------
// Stage (25600 B): A 0 (5120), Bg_h 5120, Bg_l 10240, Bu_h 15360, Bu_l 20480.
#define GU_STAGE 25600
#define GU_SMEM  (2*GU_STAGE + 1024)
#define HST2     144     // epilogue staging row stride (64 fp16 + 16B pad)

__global__ void __launch_bounds__(256, 2) k_gateup_mma(
    const float* __restrict__ x,
    const float* __restrict__ Wg,
    const float* __restrict__ Wu)
{
    extern __shared__ char smem[];
    unsigned sb = smem_u32(smem);
    int tid = threadIdx.x;
    int wid = tid >> 5, l = tid & 31;
    int wm = wid & 1, wn = wid >> 1;   // 2 x 4 warp grid, warp tile 32 x 16
    int ar = tid >> 2, ac = (tid & 3) * 8;

    int* toks = (int*)(smem + 2*GU_STAGE);
    int* sT   = (int*)(smem + 2*GU_STAGE + 512);
    const int ntot = g_nrt * 12;

    for (;;) {
        __syncthreads();    // smem reuse + sT protection across tiles
        if (tid == 0) *sT = atomicAdd(&g_tick[0], 1);
        __syncthreads();
        int t = *sT;
        if (t >= ntot) return;
        int rt   = t / 12;
        int col0 = (t - rt*12) * 64;
        int e    = g_rt_e[rt];
        int row0 = g_rt_r0[rt];
        int cnt  = g_counts[e];
        int off  = g_offsets[e];

        if (tid < 64) {
            int r = row0 + tid;
            toks[tid] = g_perm[off + ((r < cnt) ? r : (cnt - 1))] >> 2;
        }
        __syncthreads();

        const float* wg = Wg + (size_t)e * I_ * H_ + (size_t)col0 * H_;
        const float* wu = Wu + (size_t)e * I_ * H_ + (size_t)col0 * H_;

        float cg[2][2][4], cu[2][2][4];
#pragma unroll
        for (int mt = 0; mt < 2; mt++)
#pragma unroll
            for (int nt = 0; nt < 2; nt++)
#pragma unroll
                for (int j = 0; j < 4; j++) { cg[mt][nt][j] = 0.f; cu[mt][nt][j] = 0.f; }

        // ---- prologue: chunk 0 -> stage 0 ----
        {
            char* st = smem;
            const float* p = x + (size_t)toks[ar] * H_ + ac;
            *(uint4*)(st + 0 + ar*RS + ac*2) = cvtA8(*(const float4*)p, *(const float4*)(p + 4));
            uint4 hv, lv;
            const float* pg = wg + (size_t)ar * H_ + ac;
            cvtB8(*(const float4*)pg, *(const float4*)(pg + 4), hv, lv);
            *(uint4*)(st + 5120  + ar*RS + ac*2) = hv;
            *(uint4*)(st + 10240 + ar*RS + ac*2) = lv;
            const float* pu = wu + (size_t)ar * H_ + ac;
            cvtB8(*(const float4*)pu, *(const float4*)(pu + 4), hv, lv);
            *(uint4*)(st + 15360 + ar*RS + ac*2) = hv;
            *(uint4*)(st + 20480 + ar*RS + ac*2) = lv;
        }
        __syncthreads();

        const int NK = H_ / KC;   // 64
        for (int k = 0; k < NK; k++) {
            int s = k & 1;
            bool pf = (k + 1 < NK);
            float4 pa0, pa1, pg0, pg1, pu0, pu1;
            if (pf) {
                int k0 = (k + 1) * KC;
                const float* p;
                p = x + (size_t)toks[ar] * H_ + k0 + ac;  pa0 = *(const float4*)p; pa1 = *(const float4*)(p + 4);
                p = wg + (size_t)ar * H_ + k0 + ac;       pg0 = *(const float4*)p; pg1 = *(const float4*)(p + 4);
                p = wu + (size_t)ar * H_ + k0 + ac;       pu0 = *(const float4*)p; pu1 = *(const float4*)(p + 4);
            }

            unsigned stb = sb + s * GU_STAGE;
#pragma unroll
            for (int kk = 0; kk < 2; kk++) {
                unsigned ah[2][4];
#pragma unroll
                for (int mt = 0; mt < 2; mt++) {
                    unsigned arow = (unsigned)(wm*32 + mt*16 + (l & 15)) * RS;
                    unsigned ak   = (unsigned)(kk*16 + ((l >> 4) << 3)) * 2;
                    ldm4(ah[mt], stb + 0 + arow + ak);
                }
                unsigned bro = (unsigned)(wn*16 + ((l >> 4) & 1)*8 + (l & 7)) * RS
                             + (unsigned)(kk*16 + ((l >> 3) & 1)*8) * 2;
                unsigned bh[4], bl[4];
                ldm4(bh, stb + 5120  + bro);
                ldm4(bl, stb + 10240 + bro);
#pragma unroll
                for (int mt = 0; mt < 2; mt++) {
                    mma4(cg[mt][0], ah[mt], bh);   mma4(cg[mt][1], ah[mt], bh+2);
                    mma4(cg[mt][0], ah[mt], bl);   mma4(cg[mt][1], ah[mt], bl+2);
                }
                ldm4(bh, stb + 15360 + bro);
                ldm4(bl, stb + 20480 + bro);
#pragma unroll
                for (int mt = 0; mt < 2; mt++) {
                    mma4(cu[mt][0], ah[mt], bh);   mma4(cu[mt][1], ah[mt], bh+2);
                    mma4(cu[mt][0], ah[mt], bl);   mma4(cu[mt][1], ah[mt], bl+2);
                }
            }

            if (pf) {
                char* st = smem + (s ^ 1) * GU_STAGE;
                *(uint4*)(st + 0 + ar*RS + ac*2) = cvtA8(pa0, pa1);
                uint4 hv, lv;
                cvtB8(pg0, pg1, hv, lv);
                *(uint4*)(st + 5120  + ar*RS + ac*2) = hv;
                *(uint4*)(st + 10240 + ar*RS + ac*2) = lv;
                cvtB8(pu0, pu1, hv, lv);
                *(uint4*)(st + 15360 + ar*RS + ac*2) = hv;
                *(uint4*)(st + 20480 + ar*RS + ac*2) = lv;
            }
            __syncthreads();
        }

        // ---- epilogue: h = silu(g/1024)*(u/1024) -> fp16, staged for coalescing ----
        char* sh = smem;   // 64 rows x HST2 = 9216 B
#pragma unroll
        for (int mt = 0; mt < 2; mt++)
#pragma unroll
            for (int nt = 0; nt < 2; nt++)
#pragma unroll
                for (int half = 0; half < 2; half++) {
                    int rr = wm*32 + mt*16 + (l >> 2) + half*8;
                    int cc = wn*16 + nt*8 + (l & 3)*2;
                    float g0 = cg[mt][nt][2*half]   * WINV, g1 = cg[mt][nt][2*half+1] * WINV;
                    float u0 = cu[mt][nt][2*half]   * WINV, u1 = cu[mt][nt][2*half+1] * WINV;
                    float h0 = (g0 / (1.f + __expf(-g0))) * u0;
                    float h1 = (g1 / (1.f + __expf(-g1))) * u1;
                    __half2 hb = __float22half2_rn(make_float2(h0, h1));
                    *(unsigned*)(sh + rr*HST2 + cc*2) = *reinterpret_cast<unsigned*>(&hb);
                }
        __syncthreads();
#pragma unroll
        for (int j = 0; j < 2; j++) {
            int u = tid + 256*j;           // 512 slots: 64 rows x 8 uint4
            int r = u >> 3, c8 = u & 7;
            if (row0 + r < cnt) {
                size_t gidx = (size_t)(off + row0 + r) * I_ + col0 + c8*8;
                *(uint4*)&g_h[gidx] = *(uint4*)(sh + r*HST2 + c8*16);
            }
        }
    }
}

// ---------------- down mma GEMM: persistent, 64 x 128 tiles ----------------
// Stage (25600): A 0 (5120), B_h 5120 (10240), B_l 15360 (10240).
#define DN_STAGE 25600
#define DN_SMEM  (2*DN_STAGE + 1024)

__global__ void __launch_bounds__(256, 2) k_down_mma(
    const float* __restrict__ Wd,
    const float* __restrict__ ew)
{
    extern __shared__ char smem[];
    unsigned sb = smem_u32(smem);
    int tid = threadIdx.x;
    int wid = tid >> 5, l = tid & 31;
    int wm = wid & 1, wn = wid >> 1;   // 2 x 4, warp tile 32 x 32

    int* pvS = (int*)(smem + 2*DN_STAGE);
    int* sT  = (int*)(smem + 2*DN_STAGE + 512);
    const int ntot = g_nrt * 16;

    int aR = tid >> 2, aC = (tid & 3) * 8;
    int bR0 = tid >> 2,         bC0 = (tid & 3) * 8;
    int bR1 = (tid + 256) >> 2, bC1 = (tid & 3) * 8;

    for (;;) {
        __syncthreads();
        if (tid == 0) *sT = atomicAdd(&g_tick[1], 1);
        __syncthreads();
        int t = *sT;
        if (t >= ntot) return;
        int rt   = t / 16;
        int col0 = (t - rt*16) * 128;
        int e    = g_rt_e[rt];
        int row0 = g_rt_r0[rt];
        int cnt  = g_counts[e];
        int off  = g_offsets[e];

        if (tid < 64) {
            int r = row0 + tid;
            pvS[tid] = (r < cnt) ? g_perm[off + r] : -1;
        }
        __syncthreads();

        const float* wd = Wd + (size_t)e * H_ * I_ + (size_t)col0 * I_;

        float cd[2][4][4];
#pragma unroll
        for (int mt = 0; mt < 2; mt++)
#pragma unroll
            for (int nt = 0; nt < 4; nt++)
#pragma unroll
                for (int j = 0; j < 4; j++) cd[mt][nt][j] = 0.f;

        int rrA = row0 + aR;
        size_t gA = (size_t)(off + ((rrA < cnt) ? rrA : (cnt - 1))) * I_;

        // prologue: chunk 0 -> stage 0
        {
            char* st = smem;
            cpasync16(sb + 0 + aR*RS + aC*2, &g_h[gA + aC]);
            CP_COMMIT();
            uint4 hv, lv;
            const float* p;
            p = wd + (size_t)bR0 * I_ + bC0;
            cvtB8(*(const float4*)p, *(const float4*)(p + 4), hv, lv);
            *(uint4*)(st + 5120  + bR0*RS + bC0*2) = hv;
            *(uint4*)(st + 15360 + bR0*RS + bC0*2) = lv;
            p = wd + (size_t)bR1 * I_ + bC1;
            cvtB8(*(const float4*)p, *(const float4*)(p + 4), hv, lv);
            *(uint4*)(st + 5120  + bR1*RS + bC1*2) = hv;
            *(uint4*)(st + 15360 + bR1*RS + bC1*2) = lv;
            CP_WAIT0();
        }
        __syncthreads();

        const int NK = I_ / KC;   // 24
        for (int k = 0; k < NK; k++) {
            int s = k & 1;
            bool pf = (k + 1 < NK);
            float4 pb0, pb1, pb2, pb3;
            if (pf) {
                int k0 = (k + 1) * KC;
                cpasync16(sb + (s ^ 1) * DN_STAGE + 0 + aR*RS + aC*2, &g_h[gA + k0 + aC]);
                CP_COMMIT();
                const float* p;
                p = wd + (size_t)bR0 * I_ + k0 + bC0; pb0 = *(const float4*)p; pb1 = *(const float4*)(p + 4);
                p = wd + (size_t)bR1 * I_ + k0 + bC1; pb2 = *(const float4*)p; pb3 = *(const float4*)(p + 4);
            }

            unsigned stb = sb + s * DN_STAGE;
#pragma unroll
            for (int kk = 0; kk < 2; kk++) {
                unsigned ah[2][4];
#pragma unroll
                for (int mt = 0; mt < 2; mt++) {
                    unsigned arow = (unsigned)(wm*32 + mt*16 + (l & 15)) * RS;
                    unsigned ak   = (unsigned)(kk*16 + ((l >> 4) << 3)) * 2;
                    ldm4(ah[mt], stb + 0 + arow + ak);
                }
#pragma unroll
                for (int nt16 = 0; nt16 < 2; nt16++) {
                    unsigned bro = (unsigned)(wn*32 + nt16*16 + ((l >> 4) & 1)*8 + (l & 7)) * RS
                                 + (unsigned)(kk*16 + ((l >> 3) & 1)*8) * 2;
                    unsigned bh[4], bl[4];
                    ldm4(bh, stb + 5120  + bro);
                    ldm4(bl, stb + 15360 + bro);
#pragma unroll
                    for (int mt = 0; mt < 2; mt++) {
                        mma4(cd[mt][2*nt16],   ah[mt], bh);   mma4(cd[mt][2*nt16+1], ah[mt], bh+2);
                        mma4(cd[mt][2*nt16],   ah[mt], bl);   mma4(cd[mt][2*nt16+1], ah[mt], bl+2);
                    }
                }
            }

            if (pf) {
                char* st = smem + (s ^ 1) * DN_STAGE;
                uint4 hv, lv;
                cvtB8(pb0, pb1, hv, lv);
                *(uint4*)(st + 5120  + bR0*RS + bC0*2) = hv;
                *(uint4*)(st + 15360 + bR0*RS + bC0*2) = lv;
                cvtB8(pb2, pb3, hv, lv);
                *(uint4*)(st + 5120  + bR1*RS + bC1*2) = hv;
                *(uint4*)(st + 15360 + bR1*RS + bC1*2) = lv;
                CP_WAIT0();
            }
            __syncthreads();
        }

        // epilogue: scale by router weight / 1024, scatter rows of g_yp
#pragma unroll
        for (int mt = 0; mt < 2; mt++)
#pragma unroll
            for (int half = 0; half < 2; half++) {
                int rr = wm*32 + mt*16 + (l >> 2) + half*8;
                int pv = pvS[rr];
                if (pv >= 0) {
                    float w = ew[pv] * WINV;
                    size_t base = (size_t)pv * H_ + col0 + wn*32 + (l & 3)*2;
#pragma unroll
                    for (int nt = 0; nt < 4; nt++) {
                        float2 v = make_float2(w * cd[mt][nt][2*half], w * cd[mt][nt][2*half+1]);
                        *(float2*)(&g_yp[base + nt*8]) = v;
                    }
                }
            }
    }
}

// ---------------- combine ----------------
__global__ void k_combine(float* __restrict__ y) {
    int i = blockIdx.x * blockDim.x + threadIdx.x;
    if (i < T_ * H_ / 4) {
        int t  = i / (H_ / 4);
        int h4 = i - t * (H_ / 4);
        const float4* p = (const float4*)(&g_yp[(size_t)(t * K_) * H_]) + h4;
        float4 a = p[0];
        float4 b = p[H_ / 4];
        float4 c = p[2 * (H_ / 4)];
        float4 d = p[3 * (H_ / 4)];
        float4 o;
        o.x = a.x + b.x + c.x + d.x;
        o.y = a.y + b.y + c.y + d.y;
        o.z = a.z + b.z + c.z + d.z;
        o.w = a.w + b.w + c.w + d.w;
        ((float4*)y)[i] = o;
    }
}

// ---------------- launch ----------------
extern "C" void kernel_launch(void* const* d_in, const int* in_sizes, int n_in,
                              void* d_out, int out_size)
{
    const float* x   = (const float*)d_in[0];
    const float* Wg  = (const float*)d_in[1];
    const float* Wu  = (const float*)d_in[2];
    const float* Wd  = (const float*)d_in[3];
    const int*   ids = (const int*)d_in[4];
    const float* ew  = (const float*)d_in[5];
    float*       y   = (float*)d_out;

    cudaFuncSetAttribute(k_gateup_mma, cudaFuncAttributeMaxDynamicSharedMemorySize, GU_SMEM);
    cudaFuncSetAttribute(k_down_mma,   cudaFuncAttributeMaxDynamicSharedMemorySize, DN_SMEM);

    k_route<<<1, 1024>>>(ids);
    k_gateup_mma<<<NPERS, 256, GU_SMEM>>>(x, Wg, Wu);
    k_down_mma<<<NPERS, 256, DN_SMEM>>>(Wd, ew);
    k_combine<<<(T_ * H_ / 4 + 255) / 256, 256>>>(y);
}

// round 10
// speedup vs baseline: 1.4369x; 1.1616x over previous
#include <cuda_runtime.h>
#include <cuda_fp16.h>

// Problem constants
#define T_  1024
#define H_  2048
#define I_  768
#define E_  32
#define K_  4
#define NA  (T_*K_)   // 4096 assignment rows

#define KC  32
#define RS  80        // SMEM row stride bytes (32 fp16 + 16B pad) — conflict-free ldmatrix
#define WSCALE 1024.0f
#define WINV   (1.0f/1024.0f)
#define NPERS 296     // persistent CTAs (2/SM x 148)

// ---------------- portable PTX helpers ----------------
__device__ __forceinline__ unsigned smem_u32(const void* p) {
    unsigned a;
    asm("{ .reg .u64 t; cvta.to.shared.u64 t, %1; cvt.u32.u64 %0, t; }" : "=r"(a) : "l"(p));
    return a;
}

__device__ __forceinline__ void ldm4(unsigned* d, unsigned a) {
    asm volatile("ldmatrix.sync.aligned.m8n8.x4.shared.b16 {%0,%1,%2,%3}, [%4];"
        : "=r"(d[0]), "=r"(d[1]), "=r"(d[2]), "=r"(d[3]) : "r"(a));
}

__device__ __forceinline__ void mma4(float* c, const unsigned* a, const unsigned* b) {
    asm volatile("mma.sync.aligned.m16n8k16.row.col.f32.f16.f16.f32 "
        "{%0,%1,%2,%3},{%4,%5,%6,%7},{%8,%9},{%0,%1,%2,%3};"
        : "+f"(c[0]), "+f"(c[1]), "+f"(c[2]), "+f"(c[3])
        : "r"(a[0]), "r"(a[1]), "r"(a[2]), "r"(a[3]), "r"(b[0]), "r"(b[1]));
}

// L2-direct async copy (bypass L1) — used for g_h reads in the down phase
__device__ __forceinline__ void cpasync16cg(unsigned saddr, const void* g) {
    asm volatile("cp.async.cg.shared.global [%0], [%1], 16;" :: "r"(saddr), "l"(g));
}
#define CP_COMMIT() asm volatile("cp.async.commit_group;")
#define CP_WAIT0()  asm volatile("cp.async.wait_group 0;")

// 8 fp32 -> 8 plain fp16 (activations)
__device__ __forceinline__ uint4 cvtA8(float4 a, float4 b) {
    float va[8] = {a.x, a.y, a.z, a.w, b.x, b.y, b.z, b.w};
    unsigned w[4];
#pragma unroll
    for (int j = 0; j < 4; j++) {
        __half2 h = __float22half2_rn(make_float2(va[2*j], va[2*j+1]));
        w[j] = *reinterpret_cast<unsigned*>(&h);
    }
    return make_uint4(w[0], w[1], w[2], w[3]);
}

// 8 fp32 weights -> scaled (x1024) fp16 hi + lo
__device__ __forceinline__ void cvtB8(float4 a, float4 b, uint4& hi, uint4& lo) {
    float va[8] = {a.x, a.y, a.z, a.w, b.x, b.y, b.z, b.w};
    unsigned hw[4], lw[4];
#pragma unroll
    for (int j = 0; j < 4; j++) {
        float2 f = make_float2(va[2*j] * WSCALE, va[2*j+1] * WSCALE);
        __half2 h = __float22half2_rn(f);
        float2 hf = __half22float2(h);
        __half2 l = __float22half2_rn(make_float2(f.x - hf.x, f.y - hf.y));
        hw[j] = *reinterpret_cast<unsigned*>(&h);
        lw[j] = *reinterpret_cast<unsigned*>(&l);
    }
    hi = make_uint4(hw[0], hw[1], hw[2], hw[3]);
    lo = make_uint4(lw[0], lw[1], lw[2], lw[3]);
}

// ---- device scratch ----
__device__ int   g_counts[E_];
__device__ int   g_offsets[E_];
__device__ int   g_perm[NA];
__device__ int   g_nrt;
__device__ int   g_rt_e[160];
__device__ int   g_rt_r0[160];
__device__ int   g_ready[160];
__device__ int   g_tick;
__device__ __align__(16) __half g_h[(size_t)NA * I_];
__device__ __align__(16) float  g_yp[(size_t)NA * H_];

// ---------------- routing + tile list ----------------
__global__ void k_route(const int* __restrict__ ids) {
    __shared__ int cnt[E_], offs[E_], cur[E_];
    int tid = threadIdx.x;   // 1024
    if (tid < E_) { cnt[tid] = 0; cur[tid] = 0; }
    if (tid < 160) g_ready[tid] = 0;
    __syncthreads();
    for (int i = tid; i < NA; i += 1024) atomicAdd(&cnt[ids[i]], 1);
    __syncthreads();
    if (tid == 0) {
        int acc = 0, n = 0;
        for (int e = 0; e < E_; e++) {
            offs[e] = acc; g_offsets[e] = acc; g_counts[e] = cnt[e]; acc += cnt[e];
            for (int r0 = 0; r0 < cnt[e]; r0 += 64) { g_rt_e[n] = e; g_rt_r0[n] = r0; n++; }
        }
        g_nrt = n;
        g_tick = 0;
    }
    __syncthreads();
    for (int i = tid; i < NA; i += 1024) {
        int e = ids[i];
        int p = atomicAdd(&cur[e], 1);
        g_perm[offs[e] + p] = i;
    }
}

// ---------------- fused persistent MoE kernel ----------------
// SMEM: two 25600-B stages + 512 B tile metadata + tick slot.
// gateup stage: A 0 (5120), Bg_h 5120, Bg_l 10240, Bu_h 15360, Bu_l 20480
// down   stage: A 0 (5120), B_h 5120 (10240),  B_l 15360 (10240)
#define STAGE 25600
#define MOE_SMEM (2*STAGE + 1024)
#define HST2 144   // gateup epilogue staging row stride

__global__ void __launch_bounds__(256, 2) k_moe(
    const float* __restrict__ x,
    const float* __restrict__ Wg,
    const float* __restrict__ Wu,
    const float* __restrict__ Wd,
    const float* __restrict__ ew)
{
    extern __shared__ char smem[];
    unsigned sb = smem_u32(smem);
    int tid = threadIdx.x;
    int wid = tid >> 5, l = tid & 31;
    int wm = wid & 1, wn = wid >> 1;      // 2 x 4 warp grid
    int ar = tid >> 2, ac = (tid & 3) * 8;
    int bR1 = (tid + 256) >> 2;           // second B slot row (down phase)

    int* meta = (int*)(smem + 2*STAGE);   // [0..63] toks/pvS, [64] tick
    int* sT   = meta + 64;
    const int nrt = g_nrt;
    const int ngu = nrt * 12;
    const int ntot = ngu + nrt * 16;

    for (;;) {
        __syncthreads();
        if (tid == 0) *sT = atomicAdd(&g_tick, 1);
        __syncthreads();
        int t = *sT;
        if (t >= ntot) return;

        if (t < ngu) {
            // ================= gate+up tile: 64 x 64 =================
            int rt   = t / 12;
            int col0 = (t - rt*12) * 64;
            int e    = g_rt_e[rt];
            int row0 = g_rt_r0[rt];
            int cnt  = g_counts[e];
            int off  = g_offsets[e];

            if (tid < 64) {
                int r = row0 + tid;
                meta[tid] = g_perm[off + ((r < cnt) ? r : (cnt - 1))] >> 2;
            }
            __syncthreads();

            const float* wg = Wg + (size_t)e * I_ * H_ + (size_t)col0 * H_;
            const float* wu = Wu + (size_t)e * I_ * H_ + (size_t)col0 * H_;

            float cg[2][2][4], cu[2][2][4];
#pragma unroll
            for (int mt = 0; mt < 2; mt++)
#pragma unroll
                for (int nt = 0; nt < 2; nt++)
#pragma unroll
                    for (int j = 0; j < 4; j++) { cg[mt][nt][j] = 0.f; cu[mt][nt][j] = 0.f; }

            // prologue: chunk 0 -> stage 0
            {
                char* st = smem;
                const float* p = x + (size_t)meta[ar] * H_ + ac;
                *(uint4*)(st + 0 + ar*RS + ac*2) = cvtA8(*(const float4*)p, *(const float4*)(p + 4));
                uint4 hv, lv;
                const float* pg = wg + (size_t)ar * H_ + ac;
                cvtB8(*(const float4*)pg, *(const float4*)(pg + 4), hv, lv);
                *(uint4*)(st + 5120  + ar*RS + ac*2) = hv;
                *(uint4*)(st + 10240 + ar*RS + ac*2) = lv;
                const float* pu = wu + (size_t)ar * H_ + ac;
                cvtB8(*(const float4*)pu, *(const float4*)(pu + 4), hv, lv);
                *(uint4*)(st + 15360 + ar*RS + ac*2) = hv;
                *(uint4*)(st + 20480 + ar*RS + ac*2) = lv;
            }
            __syncthreads();

            const int NK = H_ / KC;   // 64
            for (int k = 0; k < NK; k++) {
                int s = k & 1;
                bool pf = (k + 1 < NK);
                float4 pa0, pa1, pg0, pg1, pu0, pu1;
                if (pf) {
                    int k0 = (k + 1) * KC;
                    const float* p;
                    p = x + (size_t)meta[ar] * H_ + k0 + ac; pa0 = *(const float4*)p; pa1 = *(const float4*)(p + 4);
                    p = wg + (size_t)ar * H_ + k0 + ac;      pg0 = *(const float4*)p; pg1 = *(const float4*)(p + 4);
                    p = wu + (size_t)ar * H_ + k0 + ac;      pu0 = *(const float4*)p; pu1 = *(const float4*)(p + 4);
                }

                unsigned stb = sb + s * STAGE;
#pragma unroll
                for (int kk = 0; kk < 2; kk++) {
                    unsigned ah[2][4];
#pragma unroll
                    for (int mt = 0; mt < 2; mt++) {
                        unsigned arow = (unsigned)(wm*32 + mt*16 + (l & 15)) * RS;
                        unsigned ak   = (unsigned)(kk*16 + ((l >> 4) << 3)) * 2;
                        ldm4(ah[mt], stb + 0 + arow + ak);
                    }
                    unsigned bro = (unsigned)(wn*16 + ((l >> 4) & 1)*8 + (l & 7)) * RS
                                 + (unsigned)(kk*16 + ((l >> 3) & 1)*8) * 2;
                    unsigned bh[4], bl[4];
                    ldm4(bh, stb + 5120  + bro);
                    ldm4(bl, stb + 10240 + bro);
#pragma unroll
                    for (int mt = 0; mt < 2; mt++) {
                        mma4(cg[mt][0], ah[mt], bh);   mma4(cg[mt][1], ah[mt], bh+2);
                        mma4(cg[mt][0], ah[mt], bl);   mma4(cg[mt][1], ah[mt], bl+2);
                    }
                    ldm4(bh, stb + 15360 + bro);
                    ldm4(bl, stb + 20480 + bro);
#pragma unroll
                    for (int mt = 0; mt < 2; mt++) {
                        mma4(cu[mt][0], ah[mt], bh);   mma4(cu[mt][1], ah[mt], bh+2);
                        mma4(cu[mt][0], ah[mt], bl);   mma4(cu[mt][1], ah[mt], bl+2);
                    }
                }

                if (pf) {
                    char* st = smem + (s ^ 1) * STAGE;
                    *(uint4*)(st + 0 + ar*RS + ac*2) = cvtA8(pa0, pa1);
                    uint4 hv, lv;
                    cvtB8(pg0, pg1, hv, lv);
                    *(uint4*)(st + 5120  + ar*RS + ac*2) = hv;
                    *(uint4*)(st + 10240 + ar*RS + ac*2) = lv;
                    cvtB8(pu0, pu1, hv, lv);
                    *(uint4*)(st + 15360 + ar*RS + ac*2) = hv;
                    *(uint4*)(st + 20480 + ar*RS + ac*2) = lv;
                }
                __syncthreads();
            }

            // epilogue: h = silu(g/1024)*(u/1024) -> fp16, staged, coalesced store
            char* sh = smem;   // 64 x HST2 = 9216 B
#pragma unroll
            for (int mt = 0; mt < 2; mt++)
#pragma unroll
                for (int nt = 0; nt < 2; nt++)
#pragma unroll
                    for (int half = 0; half < 2; half++) {
                        int rr = wm*32 + mt*16 + (l >> 2) + half*8;
                        int cc = wn*16 + nt*8 + (l & 3)*2;
                        float g0 = cg[mt][nt][2*half]   * WINV, g1 = cg[mt][nt][2*half+1] * WINV;
                        float u0 = cu[mt][nt][2*half]   * WINV, u1 = cu[mt][nt][2*half+1] * WINV;
                        float h0 = (g0 / (1.f + __expf(-g0))) * u0;
                        float h1 = (g1 / (1.f + __expf(-g1))) * u1;
                        __half2 hb = __float22half2_rn(make_float2(h0, h1));
                        *(unsigned*)(sh + rr*HST2 + cc*2) = *reinterpret_cast<unsigned*>(&hb);
                    }
            __syncthreads();
#pragma unroll
            for (int j = 0; j < 2; j++) {
                int u = tid + 256*j;       // 512 slots: 64 rows x 8 uint4
                int r = u >> 3, c8 = u & 7;
                if (row0 + r < cnt) {
                    size_t gidx = (size_t)(off + row0 + r) * I_ + col0 + c8*8;
                    *(uint4*)&g_h[gidx] = *(uint4*)(sh + r*HST2 + c8*16);
                }
            }
            __syncthreads();
            if (tid == 0) {
                __threadfence();
                atomicAdd(&g_ready[rt], 1);
            }
        } else {
            // ================= down tile: 64 x 128 =================
            int td   = t - ngu;
            int rt   = td / 16;
            int col0 = (td - rt*16) * 128;
            int e    = g_rt_e[rt];
            int row0 = g_rt_r0[rt];
            int cnt  = g_counts[e];
            int off  = g_offsets[e];

            if (tid == 0) {
                while (((volatile int*)g_ready)[rt] < 12) __nanosleep(64);
            }
            if (tid < 64) {
                int r = row0 + tid;
                meta[tid] = (r < cnt) ? g_perm[off + r] : -1;
            }
            __syncthreads();
            __threadfence();   // acquire: g_h reads below must see producer stores

            const float* wd = Wd + (size_t)e * H_ * I_ + (size_t)col0 * I_;

            float cd[2][4][4];
#pragma unroll
            for (int mt = 0; mt < 2; mt++)
#pragma unroll
                for (int nt = 0; nt < 4; nt++)
#pragma unroll
                    for (int j = 0; j < 4; j++) cd[mt][nt][j] = 0.f;

            int rrA = row0 + ar;
            size_t gA = (size_t)(off + ((rrA < cnt) ? rrA : (cnt - 1))) * I_;

            // prologue: chunk 0 -> stage 0
            {
                char* st = smem;
                cpasync16cg(sb + 0 + ar*RS + ac*2, &g_h[gA + ac]);
                CP_COMMIT();
                uint4 hv, lv;
                const float* p;
                p = wd + (size_t)ar * I_ + ac;
                cvtB8(*(const float4*)p, *(const float4*)(p + 4), hv, lv);
                *(uint4*)(st + 5120  + ar*RS + ac*2) = hv;
                *(uint4*)(st + 15360 + ar*RS + ac*2) = lv;
                p = wd + (size_t)bR1 * I_ + ac;
                cvtB8(*(const float4*)p, *(const float4*)(p + 4), hv, lv);
                *(uint4*)(st + 5120  + bR1*RS + ac*2) = hv;
                *(uint4*)(st + 15360 + bR1*RS + ac*2) = lv;
                CP_WAIT0();
            }
            __syncthreads();

            const int NK = I_ / KC;   // 24
            for (int k = 0; k < NK; k++) {
                int s = k & 1;
                bool pf = (k + 1 < NK);
                float4 pb0, pb1, pb2, pb3;
                if (pf) {
                    int k0 = (k + 1) * KC;
                    cpasync16cg(sb + (s ^ 1) * STAGE + 0 + ar*RS + ac*2, &g_h[gA + k0 + ac]);
                    CP_COMMIT();
                    const float* p;
                    p = wd + (size_t)ar * I_ + k0 + ac;  pb0 = *(const float4*)p; pb1 = *(const float4*)(p + 4);
                    p = wd + (size_t)bR1 * I_ + k0 + ac; pb2 = *(const float4*)p; pb3 = *(const float4*)(p + 4);
                }

                unsigned stb = sb + s * STAGE;
#pragma unroll
                for (int kk = 0; kk < 2; kk++) {
                    unsigned ah[2][4];
#pragma unroll
                    for (int mt = 0; mt < 2; mt++) {
                        unsigned arow = (unsigned)(wm*32 + mt*16 + (l & 15)) * RS;
                        unsigned ak   = (unsigned)(kk*16 + ((l >> 4) << 3)) * 2;
                        ldm4(ah[mt], stb + 0 + arow + ak);
                    }
#pragma unroll
                    for (int nt16 = 0; nt16 < 2; nt16++) {
                        unsigned bro = (unsigned)(wn*32 + nt16*16 + ((l >> 4) & 1)*8 + (l & 7)) * RS
                                     + (unsigned)(kk*16 + ((l >> 3) & 1)*8) * 2;
                        unsigned bh[4], bl[4];
                        ldm4(bh, stb + 5120  + bro);
                        ldm4(bl, stb + 15360 + bro);
#pragma unroll
                        for (int mt = 0; mt < 2; mt++) {
                            mma4(cd[mt][2*nt16],   ah[mt], bh);   mma4(cd[mt][2*nt16+1], ah[mt], bh+2);
                            mma4(cd[mt][2*nt16],   ah[mt], bl);   mma4(cd[mt][2*nt16+1], ah[mt], bl+2);
                        }
                    }
                }

                if (pf) {
                    char* st = smem + (s ^ 1) * STAGE;
                    uint4 hv, lv;
                    cvtB8(pb0, pb1, hv, lv);
                    *(uint4*)(st + 5120  + ar*RS + ac*2) = hv;
                    *(uint4*)(st + 15360 + ar*RS + ac*2) = lv;
                    cvtB8(pb2, pb3, hv, lv);
                    *(uint4*)(st + 5120  + bR1*RS + ac*2) = hv;
                    *(uint4*)(st + 15360 + bR1*RS + ac*2) = lv;
                    CP_WAIT0();
                }
                __syncthreads();
            }

            // epilogue: scale by router weight / 1024, scatter rows of g_yp
#pragma unroll
            for (int mt = 0; mt < 2; mt++)
#pragma unroll
                for (int half = 0; half < 2; half++) {
                    int rr = wm*32 + mt*16 + (l >> 2) + half*8;
                    int pv = meta[rr];
                    if (pv >= 0) {
                        float w = ew[pv] * WINV;
                        size_t base = (size_t)pv * H_ + col0 + wn*32 + (l & 3)*2;
#pragma unroll
                        for (int nt = 0; nt < 4; nt++) {
                            float2 v = make_float2(w * cd[mt][nt][2*half], w * cd[mt][nt][2*half+1]);
                            *(float2*)(&g_yp[base + nt*8]) = v;
                        }
                    }
                }
        }
    }
}

// ---------------- combine ----------------
__global__ void k_combine(float* __restrict__ y) {
    int i = blockIdx.x * blockDim.x + threadIdx.x;
    if (i < T_ * H_ / 4) {
        int t  = i / (H_ / 4);
        int h4 = i - t * (H_ / 4);
        const float4* p = (const float4*)(&g_yp[(size_t)(t * K_) * H_]) + h4;
        float4 a = p[0];
        float4 b = p[H_ / 4];
        float4 c = p[2 * (H_ / 4)];
        float4 d = p[3 * (H_ / 4)];
        float4 o;
        o.x = a.x + b.x + c.x + d.x;
        o.y = a.y + b.y + c.y + d.y;
        o.z = a.z + b.z + c.z + d.z;
        o.w = a.w + b.w + c.w + d.w;
        ((float4*)y)[i] = o;
    }
}

// ---------------- launch ----------------
extern "C" void kernel_launch(void* const* d_in, const int* in_sizes, int n_in,
                              void* d_out, int out_size)
{
    const float* x   = (const float*)d_in[0];
    const float* Wg  = (const float*)d_in[1];
    const float* Wu  = (const float*)d_in[2];
    const float* Wd  = (const float*)d_in[3];
    const int*   ids = (const int*)d_in[4];
    const float* ew  = (const float*)d_in[5];
    float*       y   = (float*)d_out;

    cudaFuncSetAttribute(k_moe, cudaFuncAttributeMaxDynamicSharedMemorySize, MOE_SMEM);

    k_route<<<1, 1024>>>(ids);
    k_moe<<<NPERS, 256, MOE_SMEM>>>(x, Wg, Wu, Wd, ew);
    k_combine<<<(T_ * H_ / 4 + 255) / 256, 256>>>(y);
}

// round 11
// speedup vs baseline: 1.4619x; 1.0174x over previous
#include <cuda_runtime.h>
#include <cuda_fp16.h>

// Problem constants
#define T_  1024
#define H_  2048
#define I_  768
#define E_  32
#define K_  4
#define NA  (T_*K_)   // 4096 assignment rows

#define KC  32
#define RS  80        // SMEM row stride bytes (32 fp16 + 16B pad) — conflict-free ldmatrix
#define WSCALE 1024.0f
#define WINV   (1.0f/1024.0f)
#define NPERS 296     // persistent CTAs (2/SM x 148)

// ---------------- portable PTX helpers ----------------
__device__ __forceinline__ unsigned smem_u32(const void* p) {
    unsigned a;
    asm("{ .reg .u64 t; cvta.to.shared.u64 t, %1; cvt.u32.u64 %0, t; }" : "=r"(a) : "l"(p));
    return a;
}

__device__ __forceinline__ void ldm4(unsigned* d, unsigned a) {
    asm volatile("ldmatrix.sync.aligned.m8n8.x4.shared.b16 {%0,%1,%2,%3}, [%4];"
        : "=r"(d[0]), "=r"(d[1]), "=r"(d[2]), "=r"(d[3]) : "r"(a));
}

__device__ __forceinline__ void mma4(float* c, const unsigned* a, const unsigned* b) {
    asm volatile("mma.sync.aligned.m16n8k16.row.col.f32.f16.f16.f32 "
        "{%0,%1,%2,%3},{%4,%5,%6,%7},{%8,%9},{%0,%1,%2,%3};"
        : "+f"(c[0]), "+f"(c[1]), "+f"(c[2]), "+f"(c[3])
        : "r"(a[0]), "r"(a[1]), "r"(a[2]), "r"(a[3]), "r"(b[0]), "r"(b[1]));
}

// L2-direct async copy (bypass L1) — used for g_h reads in the down phase
__device__ __forceinline__ void cpasync16cg(unsigned saddr, const void* g) {
    asm volatile("cp.async.cg.shared.global [%0], [%1], 16;" :: "r"(saddr), "l"(g));
}
#define CP_COMMIT() asm volatile("cp.async.commit_group;")
#define CP_WAIT0()  asm volatile("cp.async.wait_group 0;")

// 8 fp32 -> 8 plain fp16 (activations)
__device__ __forceinline__ uint4 cvtA8(float4 a, float4 b) {
    float va[8] = {a.x, a.y, a.z, a.w, b.x, b.y, b.z, b.w};
    unsigned w[4];
#pragma unroll
    for (int j = 0; j < 4; j++) {
        __half2 h = __float22half2_rn(make_float2(va[2*j], va[2*j+1]));
        w[j] = *reinterpret_cast<unsigned*>(&h);
    }
    return make_uint4(w[0], w[1], w[2], w[3]);
}

// 8 fp32 weights -> scaled (x1024) fp16 hi + lo
__device__ __forceinline__ void cvtB8(float4 a, float4 b, uint4& hi, uint4& lo) {
    float va[8] = {a.x, a.y, a.z, a.w, b.x, b.y, b.z, b.w};
    unsigned hw[4], lw[4];
#pragma unroll
    for (int j = 0; j < 4; j++) {
        float2 f = make_float2(va[2*j] * WSCALE, va[2*j+1] * WSCALE);
        __half2 h = __float22half2_rn(f);
        float2 hf = __half22float2(h);
        __half2 l = __float22half2_rn(make_float2(f.x - hf.x, f.y - hf.y));
        hw[j] = *reinterpret_cast<unsigned*>(&h);
        lw[j] = *reinterpret_cast<unsigned*>(&l);
    }
    hi = make_uint4(hw[0], hw[1], hw[2], hw[3]);
    lo = make_uint4(lw[0], lw[1], lw[2], lw[3]);
}

// ---- device scratch ----
__device__ int   g_counts[E_];
__device__ int   g_offsets[E_];
__device__ int   g_perm[NA];
__device__ int   g_nrt;
__device__ int   g_rt_e[160];
__device__ int   g_rt_r0[160];
__device__ int   g_rt_full[160];   // 1 = 64-row tile, 0 = 32-row remainder tile
__device__ int   g_ready[160];
__device__ int   g_tick;
__device__ __align__(16) __half g_h[(size_t)NA * I_];
__device__ __align__(16) float  g_yp[(size_t)NA * H_];

// ---------------- routing + tile list ----------------
__global__ void k_route(const int* __restrict__ ids) {
    __shared__ int cnt[E_], offs[E_], cur[E_];
    int tid = threadIdx.x;   // 1024
    if (tid < E_) { cnt[tid] = 0; cur[tid] = 0; }
    if (tid < 160) g_ready[tid] = 0;
    __syncthreads();
    for (int i = tid; i < NA; i += 1024) atomicAdd(&cnt[ids[i]], 1);
    __syncthreads();
    if (tid == 0) {
        int acc = 0, n = 0;
        for (int e = 0; e < E_; e++) {
            offs[e] = acc; g_offsets[e] = acc; g_counts[e] = cnt[e]; acc += cnt[e];
            for (int r0 = 0; r0 < cnt[e]; r0 += 64) {
                int rem = cnt[e] - r0;
                g_rt_e[n] = e; g_rt_r0[n] = r0;
                g_rt_full[n] = (rem > 32) ? 1 : 0;
                n++;
            }
        }
        g_nrt = n;
        g_tick = 0;
    }
    __syncthreads();
    for (int i = tid; i < NA; i += 1024) {
        int e = ids[i];
        int p = atomicAdd(&cur[e], 1);
        g_perm[offs[e] + p] = i;
    }
}

// ---------------- fused persistent MoE kernel ----------------
// SMEM: two 25600-B stages + 512 B tile metadata + tick slot.
// gateup stage: A 0 (5120), Bg_h 5120, Bg_l 10240, Bu_h 15360, Bu_l 20480
// down   stage: A 0 (5120), B_h 5120 (10240),  B_l 15360 (10240)
#define STAGE 25600
#define MOE_SMEM (2*STAGE + 1024)
#define HST2 144   // gateup epilogue staging row stride

__global__ void __launch_bounds__(256, 2) k_moe(
    const float* __restrict__ x,
    const float* __restrict__ Wg,
    const float* __restrict__ Wu,
    const float* __restrict__ Wd,
    const float* __restrict__ ew)
{
    extern __shared__ char smem[];
    unsigned sb = smem_u32(smem);
    int tid = threadIdx.x;
    int wid = tid >> 5, l = tid & 31;
    // wm=0 warps are wid 0..3 — one per SMSP, so 32-row tiles keep all
    // sub-partitions' tensor units busy while wm=1 warps idle.
    int wm = wid >> 2, wn = wid & 3;
    int ar = tid >> 2, ac = (tid & 3) * 8;
    int bR1 = (tid + 256) >> 2;           // second B slot row (down phase)

    int* meta = (int*)(smem + 2*STAGE);   // [0..63] toks/pvS, [64] tick
    int* sT   = meta + 64;
    const int nrt = g_nrt;
    const int ngu = nrt * 12;
    const int ntot = ngu + nrt * 16;

    for (;;) {
        __syncthreads();
        if (tid == 0) *sT = atomicAdd(&g_tick, 1);
        __syncthreads();
        int t = *sT;
        if (t >= ntot) return;

        if (t < ngu) {
            // ================= gate+up tile: (64|32) x 64 =================
            int rt   = t / 12;
            int col0 = (t - rt*12) * 64;
            int e    = g_rt_e[rt];
            int row0 = g_rt_r0[rt];
            int cnt  = g_counts[e];
            int off  = g_offsets[e];
            bool act = g_rt_full[rt] || (wm == 0);   // warp participates in MMA

            if (tid < 64) {
                int r = row0 + tid;
                meta[tid] = g_perm[off + ((r < cnt) ? r : (cnt - 1))] >> 2;
            }
            __syncthreads();

            const float* wg = Wg + (size_t)e * I_ * H_ + (size_t)col0 * H_;
            const float* wu = Wu + (size_t)e * I_ * H_ + (size_t)col0 * H_;

            float cg[2][2][4], cu[2][2][4];
#pragma unroll
            for (int mt = 0; mt < 2; mt++)
#pragma unroll
                for (int nt = 0; nt < 2; nt++)
#pragma unroll
                    for (int j = 0; j < 4; j++) { cg[mt][nt][j] = 0.f; cu[mt][nt][j] = 0.f; }

            // prologue: chunk 0 -> stage 0
            {
                char* st = smem;
                const float* p = x + (size_t)meta[ar] * H_ + ac;
                *(uint4*)(st + 0 + ar*RS + ac*2) = cvtA8(*(const float4*)p, *(const float4*)(p + 4));
                uint4 hv, lv;
                const float* pg = wg + (size_t)ar * H_ + ac;
                cvtB8(*(const float4*)pg, *(const float4*)(pg + 4), hv, lv);
                *(uint4*)(st + 5120  + ar*RS + ac*2) = hv;
                *(uint4*)(st + 10240 + ar*RS + ac*2) = lv;
                const float* pu = wu + (size_t)ar * H_ + ac;
                cvtB8(*(const float4*)pu, *(const float4*)(pu + 4), hv, lv);
                *(uint4*)(st + 15360 + ar*RS + ac*2) = hv;
                *(uint4*)(st + 20480 + ar*RS + ac*2) = lv;
            }
            __syncthreads();

            const int NK = H_ / KC;   // 64
            for (int k = 0; k < NK; k++) {
                int s = k & 1;
                bool pf = (k + 1 < NK);
                float4 pa0, pa1, pg0, pg1, pu0, pu1;
                if (pf) {
                    int k0 = (k + 1) * KC;
                    const float* p;
                    p = x + (size_t)meta[ar] * H_ + k0 + ac; pa0 = *(const float4*)p; pa1 = *(const float4*)(p + 4);
                    p = wg + (size_t)ar * H_ + k0 + ac;      pg0 = *(const float4*)p; pg1 = *(const float4*)(p + 4);
                    p = wu + (size_t)ar * H_ + k0 + ac;      pu0 = *(const float4*)p; pu1 = *(const float4*)(p + 4);
                }

                unsigned stb = sb + s * STAGE;
                if (act) {
#pragma unroll
                    for (int kk = 0; kk < 2; kk++) {
                        unsigned ah[2][4];
#pragma unroll
                        for (int mt = 0; mt < 2; mt++) {
                            unsigned arow = (unsigned)(wm*32 + mt*16 + (l & 15)) * RS;
                            unsigned ak   = (unsigned)(kk*16 + ((l >> 4) << 3)) * 2;
                            ldm4(ah[mt], stb + 0 + arow + ak);
                        }
                        unsigned bro = (unsigned)(wn*16 + ((l >> 4) & 1)*8 + (l & 7)) * RS
                                     + (unsigned)(kk*16 + ((l >> 3) & 1)*8) * 2;
                        unsigned bh[4], bl[4];
                        ldm4(bh, stb + 5120  + bro);
                        ldm4(bl, stb + 10240 + bro);
#pragma unroll
                        for (int mt = 0; mt < 2; mt++) {
                            mma4(cg[mt][0], ah[mt], bh);   mma4(cg[mt][1], ah[mt], bh+2);
                            mma4(cg[mt][0], ah[mt], bl);   mma4(cg[mt][1], ah[mt], bl+2);
                        }
                        ldm4(bh, stb + 15360 + bro);
                        ldm4(bl, stb + 20480 + bro);
#pragma unroll
                        for (int mt = 0; mt < 2; mt++) {
                            mma4(cu[mt][0], ah[mt], bh);   mma4(cu[mt][1], ah[mt], bh+2);
                            mma4(cu[mt][0], ah[mt], bl);   mma4(cu[mt][1], ah[mt], bl+2);
                        }
                    }
                }

                if (pf) {
                    char* st = smem + (s ^ 1) * STAGE;
                    *(uint4*)(st + 0 + ar*RS + ac*2) = cvtA8(pa0, pa1);
                    uint4 hv, lv;
                    cvtB8(pg0, pg1, hv, lv);
                    *(uint4*)(st + 5120  + ar*RS + ac*2) = hv;
                    *(uint4*)(st + 10240 + ar*RS + ac*2) = lv;
                    cvtB8(pu0, pu1, hv, lv);
                    *(uint4*)(st + 15360 + ar*RS + ac*2) = hv;
                    *(uint4*)(st + 20480 + ar*RS + ac*2) = lv;
                }
                __syncthreads();
            }

            // epilogue: h = silu(g/1024)*(u/1024) -> fp16, staged, coalesced store
            char* sh = smem;   // 64 x HST2 = 9216 B
            if (act) {
#pragma unroll
                for (int mt = 0; mt < 2; mt++)
#pragma unroll
                    for (int nt = 0; nt < 2; nt++)
#pragma unroll
                        for (int half = 0; half < 2; half++) {
                            int rr = wm*32 + mt*16 + (l >> 2) + half*8;
                            int cc = wn*16 + nt*8 + (l & 3)*2;
                            float g0 = cg[mt][nt][2*half]   * WINV, g1 = cg[mt][nt][2*half+1] * WINV;
                            float u0 = cu[mt][nt][2*half]   * WINV, u1 = cu[mt][nt][2*half+1] * WINV;
                            float h0 = (g0 / (1.f + __expf(-g0))) * u0;
                            float h1 = (g1 / (1.f + __expf(-g1))) * u1;
                            __half2 hb = __float22half2_rn(make_float2(h0, h1));
                            *(unsigned*)(sh + rr*HST2 + cc*2) = *reinterpret_cast<unsigned*>(&hb);
                        }
            }
            __syncthreads();
#pragma unroll
            for (int j = 0; j < 2; j++) {
                int u = tid + 256*j;       // 512 slots: 64 rows x 8 uint4
                int r = u >> 3, c8 = u & 7;
                if (row0 + r < cnt) {
                    size_t gidx = (size_t)(off + row0 + r) * I_ + col0 + c8*8;
                    *(uint4*)&g_h[gidx] = *(uint4*)(sh + r*HST2 + c8*16);
                }
            }
            __syncthreads();
            if (tid == 0) {
                __threadfence();
                atomicAdd(&g_ready[rt], 1);
            }
        } else {
            // ================= down tile: (64|32) x 128 =================
            int td   = t - ngu;
            int rt   = td / 16;
            int col0 = (td - rt*16) * 128;
            int e    = g_rt_e[rt];
            int row0 = g_rt_r0[rt];
            int cnt  = g_counts[e];
            int off  = g_offsets[e];
            bool act = g_rt_full[rt] || (wm == 0);

            if (tid == 0) {
                while (((volatile int*)g_ready)[rt] < 12) __nanosleep(64);
            }
            if (tid < 64) {
                int r = row0 + tid;
                meta[tid] = (r < cnt) ? g_perm[off + r] : -1;
            }
            __syncthreads();
            __threadfence();   // acquire: g_h reads below must see producer stores

            const float* wd = Wd + (size_t)e * H_ * I_ + (size_t)col0 * I_;

            float cd[2][4][4];
#pragma unroll
            for (int mt = 0; mt < 2; mt++)
#pragma unroll
                for (int nt = 0; nt < 4; nt++)
#pragma unroll
                    for (int j = 0; j < 4; j++) cd[mt][nt][j] = 0.f;

            int rrA = row0 + ar;
            size_t gA = (size_t)(off + ((rrA < cnt) ? rrA : (cnt - 1))) * I_;

            // prologue: chunk 0 -> stage 0
            {
                char* st = smem;
                cpasync16cg(sb + 0 + ar*RS + ac*2, &g_h[gA + ac]);
                CP_COMMIT();
                uint4 hv, lv;
                const float* p;
                p = wd + (size_t)ar * I_ + ac;
                cvtB8(*(const float4*)p, *(const float4*)(p + 4), hv, lv);
                *(uint4*)(st + 5120  + ar*RS + ac*2) = hv;
                *(uint4*)(st + 15360 + ar*RS + ac*2) = lv;
                p = wd + (size_t)bR1 * I_ + ac;
                cvtB8(*(const float4*)p, *(const float4*)(p + 4), hv, lv);
                *(uint4*)(st + 5120  + bR1*RS + ac*2) = hv;
                *(uint4*)(st + 15360 + bR1*RS + ac*2) = lv;
                CP_WAIT0();
            }
            __syncthreads();

            const int NK = I_ / KC;   // 24
            for (int k = 0; k < NK; k++) {
                int s = k & 1;
                bool pf = (k + 1 < NK);
                float4 pb0, pb1, pb2, pb3;
                if (pf) {
                    int k0 = (k + 1) * KC;
                    cpasync16cg(sb + (s ^ 1) * STAGE + 0 + ar*RS + ac*2, &g_h[gA + k0 + ac]);
                    CP_COMMIT();
                    const float* p;
                    p = wd + (size_t)ar * I_ + k0 + ac;  pb0 = *(const float4*)p; pb1 = *(const float4*)(p + 4);
                    p = wd + (size_t)bR1 * I_ + k0 + ac; pb2 = *(const float4*)p; pb3 = *(const float4*)(p + 4);
                }

                unsigned stb = sb + s * STAGE;
                if (act) {
#pragma unroll
                    for (int kk = 0; kk < 2; kk++) {
                        unsigned ah[2][4];
#pragma unroll
                        for (int mt = 0; mt < 2; mt++) {
                            unsigned arow = (unsigned)(wm*32 + mt*16 + (l & 15)) * RS;
                            unsigned ak   = (unsigned)(kk*16 + ((l >> 4) << 3)) * 2;
                            ldm4(ah[mt], stb + 0 + arow + ak);
                        }
#pragma unroll
                        for (int nt16 = 0; nt16 < 2; nt16++) {
                            unsigned bro = (unsigned)(wn*32 + nt16*16 + ((l >> 4) & 1)*8 + (l & 7)) * RS
                                         + (unsigned)(kk*16 + ((l >> 3) & 1)*8) * 2;
                            unsigned bh[4], bl[4];
                            ldm4(bh, stb + 5120  + bro);
                            ldm4(bl, stb + 15360 + bro);
#pragma unroll
                            for (int mt = 0; mt < 2; mt++) {
                                mma4(cd[mt][2*nt16],   ah[mt], bh);   mma4(cd[mt][2*nt16+1], ah[mt], bh+2);
                                mma4(cd[mt][2*nt16],   ah[mt], bl);   mma4(cd[mt][2*nt16+1], ah[mt], bl+2);
                            }
                        }
                    }
                }

                if (pf) {
                    char* st = smem + (s ^ 1) * STAGE;
                    uint4 hv, lv;
                    cvtB8(pb0, pb1, hv, lv);
                    *(uint4*)(st + 5120  + ar*RS + ac*2) = hv;
                    *(uint4*)(st + 15360 + ar*RS + ac*2) = lv;
                    cvtB8(pb2, pb3, hv, lv);
                    *(uint4*)(st + 5120  + bR1*RS + ac*2) = hv;
                    *(uint4*)(st + 15360 + bR1*RS + ac*2) = lv;
                    CP_WAIT0();
                }
                __syncthreads();
            }

            // epilogue: scale by router weight / 1024, scatter rows of g_yp
            if (act) {
#pragma unroll
                for (int mt = 0; mt < 2; mt++)
#pragma unroll
                    for (int half = 0; half < 2; half++) {
                        int rr = wm*32 + mt*16 + (l >> 2) + half*8;
                        int pv = meta[rr];
                        if (pv >= 0) {
                            float w = ew[pv] * WINV;
                            size_t base = (size_t)pv * H_ + col0 + wn*32 + (l & 3)*2;
#pragma unroll
                            for (int nt = 0; nt < 4; nt++) {
                                float2 v = make_float2(w * cd[mt][nt][2*half], w * cd[mt][nt][2*half+1]);
                                *(float2*)(&g_yp[base + nt*8]) = v;
                            }
                        }
                    }
            }
        }
    }
}

// ---------------- combine ----------------
__global__ void k_combine(float* __restrict__ y) {
    int i = blockIdx.x * blockDim.x + threadIdx.x;
    if (i < T_ * H_ / 4) {
        int t  = i / (H_ / 4);
        int h4 = i - t * (H_ / 4);
        const float4* p = (const float4*)(&g_yp[(size_t)(t * K_) * H_]) + h4;
        float4 a = p[0];
        float4 b = p[H_ / 4];
        float4 c = p[2 * (H_ / 4)];
        float4 d = p[3 * (H_ / 4)];
        float4 o;
        o.x = a.x + b.x + c.x + d.x;
        o.y = a.y + b.y + c.y + d.y;
        o.z = a.z + b.z + c.z + d.z;
        o.w = a.w + b.w + c.w + d.w;
        ((float4*)y)[i] = o;
    }
}

// ---------------- launch ----------------
extern "C" void kernel_launch(void* const* d_in, const int* in_sizes, int n_in,
                              void* d_out, int out_size)
{
    const float* x   = (const float*)d_in[0];
    const float* Wg  = (const float*)d_in[1];
    const float* Wu  = (const float*)d_in[2];
    const float* Wd  = (const float*)d_in[3];
    const int*   ids = (const int*)d_in[4];
    const float* ew  = (const float*)d_in[5];
    float*       y   = (float*)d_out;

    cudaFuncSetAttribute(k_moe, cudaFuncAttributeMaxDynamicSharedMemorySize, MOE_SMEM);

    k_route<<<1, 1024>>>(ids);
    k_moe<<<NPERS, 256, MOE_SMEM>>>(x, Wg, Wu, Wd, ew);
    k_combine<<<(T_ * H_ / 4 + 255) / 256, 256>>>(y);
}